// round 8
// baseline (speedup 1.0000x reference)
#include <cuda_runtime.h>
#include <cuda_bf16.h>
#include <math.h>
#include <stdint.h>

#define BB     4
#define NSEQ   8192
#define DM     512
#define MTOT   (BB * NSEQ)       // 32768
#define SPLITK 32
#define KC     (NSEQ / SPLITK)   // 256

// ---------------- scratch (static device memory; referenced ONLY from device
// code — host-side use of these symbols silently hits host memory via ATS) ---
__device__ float g_P [SPLITK * BB * DM * DM];   // X^T X split-K partials
__device__ float g_G [BB * DM * DM];            // X^T X
__device__ float g_M1[BB * DM * DM];            // Wv @ G
__device__ float g_Pm[BB * 16 * DM];
__device__ float g_xm[BB * DM];
__device__ float g_first[BB * DM];
__device__ __nv_bfloat16 g_Xhi[(size_t)MTOT * DM];   // bf16 split of X
__device__ __nv_bfloat16 g_Xlo[(size_t)MTOT * DM];
__device__ __nv_bfloat16 g_KVthi[BB * DM * DM];      // bf16 split of KV^T [j,k]
__device__ __nv_bfloat16 g_KVtlo[BB * DM * DM];

__constant__ int c_ti[10] = {0,0,0,0,1,1,1,2,2,3};
__constant__ int c_tj[10] = {0,1,2,3,1,2,3,2,3,3};

#define SW128(x) ((x) ^ (((x) >> 3) & 0x70))

__device__ __forceinline__ uint32_t smem_to_u32(const void* p) {
    uint32_t a;
    asm("{ .reg .u64 t; cvta.to.shared.u64 t, %1; cvt.u32.u64 %0, t; }"
        : "=r"(a) : "l"(p));
    return a;
}
__device__ __forceinline__ void ldmx4(uint32_t r[4], uint32_t addr) {
    asm volatile("ldmatrix.sync.aligned.m8n8.x4.shared.b16 {%0,%1,%2,%3}, [%4];"
        : "=r"(r[0]), "=r"(r[1]), "=r"(r[2]), "=r"(r[3]) : "r"(addr));
}
__device__ __forceinline__ void mma16816(float c[4], const uint32_t a[4],
                                         const uint32_t b[2]) {
    asm volatile("mma.sync.aligned.m16n8k16.row.col.f32.bf16.bf16.f32 "
        "{%0,%1,%2,%3}, {%4,%5,%6,%7}, {%8,%9}, {%0,%1,%2,%3};"
        : "+f"(c[0]), "+f"(c[1]), "+f"(c[2]), "+f"(c[3])
        : "r"(a[0]), "r"(a[1]), "r"(a[2]), "r"(a[3]), "r"(b[0]), "r"(b[1]));
}

// ============================================================================
// bf16 split of X: hi = bf16(x), lo = bf16(x - hi). 8 elems/thread.
// ============================================================================
__global__ void convert_x_kernel(const float* __restrict__ X)
{
    const size_t base = ((size_t)blockIdx.x * 256 + threadIdx.x) * 8;
    float4 v0 = *(const float4*)(X + base);
    float4 v1 = *(const float4*)(X + base + 4);
    float v[8] = {v0.x, v0.y, v0.z, v0.w, v1.x, v1.y, v1.z, v1.w};
    uint4 uh, ul;
    __nv_bfloat16* ph = (__nv_bfloat16*)&uh;
    __nv_bfloat16* pl = (__nv_bfloat16*)&ul;
#pragma unroll
    for (int j = 0; j < 8; j++) {
        __nv_bfloat16 h = __float2bfloat16(v[j]);
        ph[j] = h;
        pl[j] = __float2bfloat16(v[j] - __bfloat162float(h));
    }
    *(uint4*)(g_Xhi + base) = uh;
    *(uint4*)(g_Xlo + base) = ul;
}

// ============================================================================
// X^T X (fp32 FFMA, split-K, upper-triangle tiles), double-buffered. UNCHANGED.
// ============================================================================
__global__ void __launch_bounds__(256, 2) xtx_kernel(const float* __restrict__ X)
{
    __shared__ float As[2][16][128];
    __shared__ float Bs[2][16][128];
    const int tid = threadIdx.x;
    const int ti  = c_ti[blockIdx.x];
    const int tj  = c_tj[blockIdx.x];
    const int b   = blockIdx.y / SPLITK;
    const int s   = blockIdx.y % SPLITK;
    const float* __restrict__ base = X + ((size_t)b * NSEQ + (size_t)s * KC) * DM;
    const float* __restrict__ Ab = base + ti * 128;
    const float* __restrict__ Bb = base + tj * 128;

    const int kr0 = tid >> 5;
    const int kr1 = kr0 + 8;
    const int cq0 = (tid & 31) << 2;
    const int tx  = tid & 15;
    const int ty  = tid >> 4;

    float acc[8][8];
#pragma unroll
    for (int i = 0; i < 8; i++)
#pragma unroll
        for (int j = 0; j < 8; j++) acc[i][j] = 0.f;

    float4 a0 = *(const float4*)(Ab + (size_t)kr0 * DM + cq0);
    float4 a1 = *(const float4*)(Ab + (size_t)kr1 * DM + cq0);
    float4 b0 = *(const float4*)(Bb + (size_t)kr0 * DM + cq0);
    float4 b1 = *(const float4*)(Bb + (size_t)kr1 * DM + cq0);
    *(float4*)&As[0][kr0][cq0] = a0;
    *(float4*)&As[0][kr1][cq0] = a1;
    *(float4*)&Bs[0][kr0][cq0] = b0;
    *(float4*)&Bs[0][kr1][cq0] = b1;
    __syncthreads();

    const int NK = KC / 16;
    for (int kt = 0; kt < NK; kt++) {
        const int cur = kt & 1;
        if (kt + 1 < NK) {
            const float* An = Ab + (size_t)(kt + 1) * 16 * DM;
            const float* Bn = Bb + (size_t)(kt + 1) * 16 * DM;
            a0 = *(const float4*)(An + (size_t)kr0 * DM + cq0);
            a1 = *(const float4*)(An + (size_t)kr1 * DM + cq0);
            b0 = *(const float4*)(Bn + (size_t)kr0 * DM + cq0);
            b1 = *(const float4*)(Bn + (size_t)kr1 * DM + cq0);
        }
#pragma unroll
        for (int k = 0; k < 16; k++) {
            float a[8], bb[8];
            *(float4*)(a)      = *(const float4*)&As[cur][k][ty * 8];
            *(float4*)(a + 4)  = *(const float4*)&As[cur][k][ty * 8 + 4];
            *(float4*)(bb)     = *(const float4*)&Bs[cur][k][tx * 8];
            *(float4*)(bb + 4) = *(const float4*)&Bs[cur][k][tx * 8 + 4];
#pragma unroll
            for (int i = 0; i < 8; i++)
#pragma unroll
                for (int j = 0; j < 8; j++)
                    acc[i][j] = fmaf(a[i], bb[j], acc[i][j]);
        }
        if (kt + 1 < NK) {
            const int nxt = cur ^ 1;
            *(float4*)&As[nxt][kr0][cq0] = a0;
            *(float4*)&As[nxt][kr1][cq0] = a1;
            *(float4*)&Bs[nxt][kr0][cq0] = b0;
            *(float4*)&Bs[nxt][kr1][cq0] = b1;
        }
        __syncthreads();
    }

    float* C = g_P + ((size_t)(s * BB + b)) * DM * DM;
#pragma unroll
    for (int i = 0; i < 8; i++) {
        float* crow = C + (size_t)(ti * 128 + ty * 8 + i) * DM + tj * 128 + tx * 8;
        *(float4*)(crow)     = make_float4(acc[i][0], acc[i][1], acc[i][2], acc[i][3]);
        *(float4*)(crow + 4) = make_float4(acc[i][4], acc[i][5], acc[i][6], acc[i][7]);
    }
}

__global__ void reduce_g_kernel()
{
    const int idx = blockIdx.x * 256 + threadIdx.x;
    const int b = idx >> 18;
    const int r = idx & (DM * DM - 1);
    const int i = r >> 9;
    const int j = r & 511;
    if (j < i) return;
    float s = 0.f;
#pragma unroll
    for (int sp = 0; sp < SPLITK; sp++)
        s += g_P[((size_t)(sp * BB + b)) * DM * DM + r];
    g_G[(size_t)b * DM * DM + (size_t)i * DM + j] = s;
    g_G[(size_t)b * DM * DM + (size_t)j * DM + i] = s;
}

__global__ void meanx1_kernel(const float* __restrict__ X)
{
    const int b  = blockIdx.x;
    const int jt = blockIdx.y;
    const int ch = blockIdx.z;
    const int j  = jt * 128 + threadIdx.x;
    const float* base = X + ((size_t)b * NSEQ + (size_t)ch * 512) * DM + j;
    float s0 = 0.f, s1 = 0.f, s2 = 0.f, s3 = 0.f;
    for (int i = 0; i < 512; i += 4) {
        s0 += base[(size_t)(i + 0) * DM];
        s1 += base[(size_t)(i + 1) * DM];
        s2 += base[(size_t)(i + 2) * DM];
        s3 += base[(size_t)(i + 3) * DM];
    }
    g_Pm[(b * 16 + ch) * DM + j] = (s0 + s1) + (s2 + s3);
}

__global__ void meanx2_kernel()
{
    const int b = blockIdx.x;
    const int j = blockIdx.y * 128 + threadIdx.x;
    float s = 0.f;
#pragma unroll
    for (int c = 0; c < 16; c++) s += g_Pm[(b * 16 + c) * DM + j];
    g_xm[b * DM + j] = s * (1.0f / (float)NSEQ);
}

__global__ void first_kernel(const float* __restrict__ Wv)
{
    const int b    = blockIdx.x;
    const int j    = blockIdx.y * 8 + (threadIdx.x >> 5);
    const int lane = threadIdx.x & 31;
    const float* xm = g_xm + b * DM;
    const float* w  = Wv + (size_t)j * DM;
    float s = 0.f;
    for (int k = lane; k < DM; k += 32) s += xm[k] * w[k];
#pragma unroll
    for (int o = 16; o; o >>= 1) s += __shfl_xor_sync(0xFFFFFFFFu, s, o);
    if (lane == 0) g_first[b * DM + j] = s;
}

// ============================================================================
// small batched 512^3 GEMM. mode 0: M1[b] = Wv @ G[b] (NN, fp32 out).
// mode 1: KVt[b] = M1[b] @ Wtheta^T (NT) -> bf16 hi/lo split output.
// (KV^T = Wv G Wtheta^T since G is symmetric.)
// ============================================================================
__global__ void __launch_bounds__(128) small_gemm_kernel(
    const float* __restrict__ W, int mode)
{
    __shared__ float As[16][68];
    __shared__ float Bs[16][68];
    const int tid = threadIdx.x;
    const int i0  = blockIdx.x * 64;
    const int j0  = blockIdx.y * 64;
    const int b   = blockIdx.z;
    const size_t bo = (size_t)b * DM * DM;
    const float* __restrict__ A = (mode == 0) ? W : (g_M1 + bo);
    const float* __restrict__ B = (mode == 0) ? (g_G + bo) : W;
    const int transB = mode;

    const int tx = tid & 15;
    const int ty = tid >> 4;
    const int r0  = tid >> 2;
    const int r1  = r0 + 32;
    const int kq0 = (tid & 3) << 2;
    const int kr0 = tid >> 4;
    const int kr1 = kr0 + 8;
    const int cq0 = (tid & 15) << 2;

    float acc[8][4];
#pragma unroll
    for (int i = 0; i < 8; i++)
#pragma unroll
        for (int j = 0; j < 4; j++) acc[i][j] = 0.f;

    for (int k0 = 0; k0 < DM; k0 += 16) {
        float4 va0 = *(const float4*)(A + (size_t)(i0 + r0) * DM + k0 + kq0);
        float4 va1 = *(const float4*)(A + (size_t)(i0 + r1) * DM + k0 + kq0);
        As[kq0 + 0][r0] = va0.x; As[kq0 + 1][r0] = va0.y;
        As[kq0 + 2][r0] = va0.z; As[kq0 + 3][r0] = va0.w;
        As[kq0 + 0][r1] = va1.x; As[kq0 + 1][r1] = va1.y;
        As[kq0 + 2][r1] = va1.z; As[kq0 + 3][r1] = va1.w;
        if (transB) {
            float4 vb0 = *(const float4*)(B + (size_t)(j0 + r0) * DM + k0 + kq0);
            float4 vb1 = *(const float4*)(B + (size_t)(j0 + r1) * DM + k0 + kq0);
            Bs[kq0 + 0][r0] = vb0.x; Bs[kq0 + 1][r0] = vb0.y;
            Bs[kq0 + 2][r0] = vb0.z; Bs[kq0 + 3][r0] = vb0.w;
            Bs[kq0 + 0][r1] = vb1.x; Bs[kq0 + 1][r1] = vb1.y;
            Bs[kq0 + 2][r1] = vb1.z; Bs[kq0 + 3][r1] = vb1.w;
        } else {
            float4 vb0 = *(const float4*)(B + (size_t)(k0 + kr0) * DM + j0 + cq0);
            float4 vb1 = *(const float4*)(B + (size_t)(k0 + kr1) * DM + j0 + cq0);
            *(float4*)&Bs[kr0][cq0] = vb0;
            *(float4*)&Bs[kr1][cq0] = vb1;
        }
        __syncthreads();
#pragma unroll
        for (int k = 0; k < 16; k++) {
            float a[8], bb[4];
            *(float4*)(a)     = *(const float4*)&As[k][ty * 8];
            *(float4*)(a + 4) = *(const float4*)&As[k][ty * 8 + 4];
            *(float4*)(bb)    = *(const float4*)&Bs[k][tx * 4];
#pragma unroll
            for (int i = 0; i < 8; i++)
#pragma unroll
                for (int j = 0; j < 4; j++)
                    acc[i][j] = fmaf(a[i], bb[j], acc[i][j]);
        }
        __syncthreads();
    }

    if (mode == 0) {
#pragma unroll
        for (int i = 0; i < 8; i++)
            *(float4*)(g_M1 + bo + (size_t)(i0 + ty * 8 + i) * DM + j0 + tx * 4) =
                make_float4(acc[i][0], acc[i][1], acc[i][2], acc[i][3]);
    } else {
#pragma unroll
        for (int i = 0; i < 8; i++) {
            size_t o = bo + (size_t)(i0 + ty * 8 + i) * DM + j0 + tx * 4;
#pragma unroll
            for (int j = 0; j < 4; j++) {
                float v = acc[i][j];
                __nv_bfloat16 h = __float2bfloat16(v);
                g_KVthi[o + j] = h;
                g_KVtlo[o + j] = __float2bfloat16(v - __bfloat162float(h));
            }
        }
    }
}

// ============================================================================
// final GEMM on HMMA (mma.sync m16n8k16 bf16, base PTX ISA — tcgen05 is not
// available on this toolchain's .target sm_103):
//   out[m,j] = first[b][j] + scale * sum_k X[m,k] KV[k,j]
//   D = Ahi Bhi^T + Ahi Blo^T + Alo Bhi^T   (3-term bf16 split, fp32 accum)
// CTA 128x128, 8 warps (2x4), warp tile 64x32. K-chunks of 64 in smem, SW128.
// grid (DM/128, MTOT/128) — n fastest so CTAs sharing an X strip are adjacent.
// ============================================================================
#define SM_AHI 0
#define SM_ALO 16384
#define SM_BHI 32768
#define SM_BLO 49152
#define FIN_SMEM 65536

__global__ void __launch_bounds__(256, 2) final_mma_kernel(float* __restrict__ out)
{
    extern __shared__ char smem[];
    const uint32_t sb = smem_to_u32(smem);
    const int tid  = threadIdx.x;
    const int wid  = tid >> 5;
    const int lane = tid & 31;
    const int wm   = wid >> 2;          // 0..1 (64-row halves)
    const int wn   = wid & 3;           // 0..3 (32-col quarters)
    const int n0   = blockIdx.x * 128;
    const int m0   = blockIdx.y * 128;
    const int b    = m0 / NSEQ;
    const size_t kvb = (size_t)b * DM * DM;

    // ldmatrix per-lane row/byte components
    const int a_row = wm * 64 + ((lane >> 3) & 1) * 8 + (lane & 7);
    const int a_byt = ((lane >> 4) & 1) * 16;
    const int b_row = wn * 32 + ((lane >> 4) & 1) * 8 + (lane & 7);
    const int b_byt = ((lane >> 3) & 1) * 16;

    float acc[4][4][4];
#pragma unroll
    for (int mt = 0; mt < 4; mt++)
#pragma unroll
        for (int nt = 0; nt < 4; nt++)
#pragma unroll
            for (int q = 0; q < 4; q++) acc[mt][nt][q] = 0.f;

    for (int kc = 0; kc < 8; kc++) {
        // stage chunk: 4 tiles of [128 rows][64 bf16], SW128-swizzled 128B rows
        for (int i = tid; i < 1024; i += 256) {
            const int row = i >> 3;
            const int cg  = i & 7;
            const uint32_t sw = SW128((uint32_t)(row * 128 + cg * 16));
            const size_t ga = (size_t)(m0 + row) * DM + kc * 64 + cg * 8;
            const size_t gb = kvb + (size_t)(n0 + row) * DM + kc * 64 + cg * 8;
            *(uint4*)(smem + SM_AHI + sw) = *(const uint4*)(g_Xhi + ga);
            *(uint4*)(smem + SM_ALO + sw) = *(const uint4*)(g_Xlo + ga);
            *(uint4*)(smem + SM_BHI + sw) = *(const uint4*)(g_KVthi + gb);
            *(uint4*)(smem + SM_BLO + sw) = *(const uint4*)(g_KVtlo + gb);
        }
        __syncthreads();

#pragma unroll
        for (int kk = 0; kk < 4; kk++) {
            uint32_t a[4][4], bb[4][2];
            // A hi
#pragma unroll
            for (int mt = 0; mt < 4; mt++) {
                uint32_t off = (uint32_t)((a_row + mt * 16) * 128 + kk * 32 + a_byt);
                ldmx4(a[mt], sb + SM_AHI + SW128(off));
            }
            // B hi
#pragma unroll
            for (int p = 0; p < 2; p++) {
                uint32_t off = (uint32_t)((b_row + p * 16) * 128 + kk * 32 + b_byt);
                uint32_t r[4];
                ldmx4(r, sb + SM_BHI + SW128(off));
                bb[p * 2][0] = r[0]; bb[p * 2][1] = r[1];
                bb[p * 2 + 1][0] = r[2]; bb[p * 2 + 1][1] = r[3];
            }
#pragma unroll
            for (int mt = 0; mt < 4; mt++)
#pragma unroll
                for (int nt = 0; nt < 4; nt++)
                    mma16816(acc[mt][nt], a[mt], bb[nt]);      // Ahi*Bhi
            // B lo
#pragma unroll
            for (int p = 0; p < 2; p++) {
                uint32_t off = (uint32_t)((b_row + p * 16) * 128 + kk * 32 + b_byt);
                uint32_t r[4];
                ldmx4(r, sb + SM_BLO + SW128(off));
                bb[p * 2][0] = r[0]; bb[p * 2][1] = r[1];
                bb[p * 2 + 1][0] = r[2]; bb[p * 2 + 1][1] = r[3];
            }
#pragma unroll
            for (int mt = 0; mt < 4; mt++)
#pragma unroll
                for (int nt = 0; nt < 4; nt++)
                    mma16816(acc[mt][nt], a[mt], bb[nt]);      // Ahi*Blo
            // A lo + reload B hi
#pragma unroll
            for (int mt = 0; mt < 4; mt++) {
                uint32_t off = (uint32_t)((a_row + mt * 16) * 128 + kk * 32 + a_byt);
                ldmx4(a[mt], sb + SM_ALO + SW128(off));
            }
#pragma unroll
            for (int p = 0; p < 2; p++) {
                uint32_t off = (uint32_t)((b_row + p * 16) * 128 + kk * 32 + b_byt);
                uint32_t r[4];
                ldmx4(r, sb + SM_BHI + SW128(off));
                bb[p * 2][0] = r[0]; bb[p * 2][1] = r[1];
                bb[p * 2 + 1][0] = r[2]; bb[p * 2 + 1][1] = r[3];
            }
#pragma unroll
            for (int mt = 0; mt < 4; mt++)
#pragma unroll
                for (int nt = 0; nt < 4; nt++)
                    mma16816(acc[mt][nt], a[mt], bb[nt]);      // Alo*Bhi
        }
        __syncthreads();
    }

    // epilogue: c0,c1 -> row g, cols 2t,2t+1; c2,c3 -> row g+8
    const float scale = 1.0f / (8192.0f * sqrtf(512.0f));
    const int g = lane >> 2;
    const int t = lane & 3;
#pragma unroll
    for (int mt = 0; mt < 4; mt++) {
        const int r = m0 + wm * 64 + mt * 16 + g;
#pragma unroll
        for (int nt = 0; nt < 4; nt++) {
            const int c = n0 + wn * 32 + nt * 8 + t * 2;
            const float f0 = g_first[b * DM + c];
            const float f1 = g_first[b * DM + c + 1];
            *(float2*)(out + (size_t)r * DM + c) =
                make_float2(f0 + scale * acc[mt][nt][0],
                            f1 + scale * acc[mt][nt][1]);
            *(float2*)(out + (size_t)(r + 8) * DM + c) =
                make_float2(f0 + scale * acc[mt][nt][2],
                            f1 + scale * acc[mt][nt][3]);
        }
    }
}

// ============================================================================
extern "C" void kernel_launch(void* const* d_in, const int* in_sizes, int n_in,
                              void* d_out, int out_size)
{
    (void)in_sizes; (void)n_in; (void)out_size;
    const float* X  = (const float*)d_in[0];
    const float* Wv = (const float*)d_in[1];
    const float* Wt = (const float*)d_in[2];
    float* out = (float*)d_out;

    cudaFuncSetAttribute(final_mma_kernel,
                         cudaFuncAttributeMaxDynamicSharedMemorySize, FIN_SMEM);

    // 0) bf16 hi/lo split of X
    convert_x_kernel<<<dim3((MTOT * DM) / (256 * 8)), 256>>>(X);
    // 1) G[b] = X[b]^T X[b]  (fp32, split-K, upper-triangle)
    xtx_kernel<<<dim3(10, BB * SPLITK), 256>>>(X);
    // 2) mean over n of X, then first = mean(X) @ Wv^T
    meanx1_kernel<<<dim3(BB, 4, 16), 128>>>(X);
    meanx2_kernel<<<dim3(BB, 4), 128>>>();
    first_kernel<<<dim3(BB, 64), 256>>>(Wv);
    // 3) reduce + mirror G
    reduce_g_kernel<<<dim3((BB * DM * DM) / 256), 256>>>();
    // 4) M1[b] = Wv @ G[b]; KVt[b] = M1[b] @ Wtheta^T (bf16 hi/lo out)
    small_gemm_kernel<<<dim3(8, 8, BB), 128>>>(Wv, 0);
    small_gemm_kernel<<<dim3(8, 8, BB), 128>>>(Wt, 1);
    // 5) out = first + scale * X @ KV   (HMMA bf16 3-term split)
    final_mma_kernel<<<dim3(DM / 128, MTOT / 128), 256, FIN_SMEM>>>(out);
}

// round 9
// speedup vs baseline: 1.7730x; 1.7730x over previous
#include <cuda_runtime.h>
#include <cuda_fp16.h>
#include <math.h>
#include <stdint.h>

#define BB     4
#define NSEQ   8192
#define DM     512
#define MTOT   (BB * NSEQ)       // 32768
#define SPLITK 32
#define KC     (NSEQ / SPLITK)   // 256
#define MCH    32                // meanx chunks

// ---------------- scratch (static device memory; referenced ONLY from device
// code — host-side use of these symbols silently hits host memory via ATS) ---
__device__ float g_P [SPLITK * BB * DM * DM];   // X^T X split-K partials
__device__ float g_G [BB * DM * DM];            // X^T X
__device__ float g_M1[BB * DM * DM];            // Wv @ G
__device__ float g_Pm[BB * MCH * DM];
__device__ float g_xm[BB * DM];
__device__ float g_first[BB * DM];
__device__ __half g_Xh [(size_t)MTOT * DM];     // fp16 X
__device__ __half g_KVh[BB * DM * DM];          // fp16 KV^T [j,k]

__constant__ int c_ti[10] = {0,0,0,0,1,1,1,2,2,3};
__constant__ int c_tj[10] = {0,1,2,3,1,2,3,2,3,3};

#define SW128(x) ((x) ^ (((x) >> 3) & 0x70))

__device__ __forceinline__ uint32_t smem_to_u32(const void* p) {
    uint32_t a;
    asm("{ .reg .u64 t; cvta.to.shared.u64 t, %1; cvt.u32.u64 %0, t; }"
        : "=r"(a) : "l"(p));
    return a;
}
__device__ __forceinline__ void ldmx4(uint32_t r[4], uint32_t addr) {
    asm volatile("ldmatrix.sync.aligned.m8n8.x4.shared.b16 {%0,%1,%2,%3}, [%4];"
        : "=r"(r[0]), "=r"(r[1]), "=r"(r[2]), "=r"(r[3]) : "r"(addr));
}
__device__ __forceinline__ void mma16816(float c[4], const uint32_t a[4],
                                         const uint32_t b[2]) {
    asm volatile("mma.sync.aligned.m16n8k16.row.col.f32.f16.f16.f32 "
        "{%0,%1,%2,%3}, {%4,%5,%6,%7}, {%8,%9}, {%0,%1,%2,%3};"
        : "+f"(c[0]), "+f"(c[1]), "+f"(c[2]), "+f"(c[3])
        : "r"(a[0]), "r"(a[1]), "r"(a[2]), "r"(a[3]), "r"(b[0]), "r"(b[1]));
}
__device__ __forceinline__ void cp_async16(uint32_t dst, const void* src) {
    asm volatile("cp.async.cg.shared.global [%0], [%1], 16;"
        :: "r"(dst), "l"(src) : "memory");
}
#define CP_COMMIT() asm volatile("cp.async.commit_group;" ::: "memory")
#define CP_WAIT(n)  asm volatile("cp.async.wait_group %0;" :: "n"(n) : "memory")

// ============================================================================
// fp16 conversion of X. 8 elems/thread.
// ============================================================================
__global__ void convert_x_kernel(const float* __restrict__ X)
{
    const size_t base = ((size_t)blockIdx.x * 256 + threadIdx.x) * 8;
    float4 v0 = *(const float4*)(X + base);
    float4 v1 = *(const float4*)(X + base + 4);
    float v[8] = {v0.x, v0.y, v0.z, v0.w, v1.x, v1.y, v1.z, v1.w};
    uint4 u;
    __half* ph = (__half*)&u;
#pragma unroll
    for (int j = 0; j < 8; j++) ph[j] = __float2half_rn(v[j]);
    *(uint4*)(g_Xh + base) = u;
}

// ============================================================================
// X^T X (fp32 FFMA, split-K, upper-triangle tiles), double-buffered. UNCHANGED.
// ============================================================================
__global__ void __launch_bounds__(256, 2) xtx_kernel(const float* __restrict__ X)
{
    __shared__ float As[2][16][128];
    __shared__ float Bs[2][16][128];
    const int tid = threadIdx.x;
    const int ti  = c_ti[blockIdx.x];
    const int tj  = c_tj[blockIdx.x];
    const int b   = blockIdx.y / SPLITK;
    const int s   = blockIdx.y % SPLITK;
    const float* __restrict__ base = X + ((size_t)b * NSEQ + (size_t)s * KC) * DM;
    const float* __restrict__ Ab = base + ti * 128;
    const float* __restrict__ Bb = base + tj * 128;

    const int kr0 = tid >> 5;
    const int kr1 = kr0 + 8;
    const int cq0 = (tid & 31) << 2;
    const int tx  = tid & 15;
    const int ty  = tid >> 4;

    float acc[8][8];
#pragma unroll
    for (int i = 0; i < 8; i++)
#pragma unroll
        for (int j = 0; j < 8; j++) acc[i][j] = 0.f;

    float4 a0 = *(const float4*)(Ab + (size_t)kr0 * DM + cq0);
    float4 a1 = *(const float4*)(Ab + (size_t)kr1 * DM + cq0);
    float4 b0 = *(const float4*)(Bb + (size_t)kr0 * DM + cq0);
    float4 b1 = *(const float4*)(Bb + (size_t)kr1 * DM + cq0);
    *(float4*)&As[0][kr0][cq0] = a0;
    *(float4*)&As[0][kr1][cq0] = a1;
    *(float4*)&Bs[0][kr0][cq0] = b0;
    *(float4*)&Bs[0][kr1][cq0] = b1;
    __syncthreads();

    const int NK = KC / 16;
    for (int kt = 0; kt < NK; kt++) {
        const int cur = kt & 1;
        if (kt + 1 < NK) {
            const float* An = Ab + (size_t)(kt + 1) * 16 * DM;
            const float* Bn = Bb + (size_t)(kt + 1) * 16 * DM;
            a0 = *(const float4*)(An + (size_t)kr0 * DM + cq0);
            a1 = *(const float4*)(An + (size_t)kr1 * DM + cq0);
            b0 = *(const float4*)(Bn + (size_t)kr0 * DM + cq0);
            b1 = *(const float4*)(Bn + (size_t)kr1 * DM + cq0);
        }
#pragma unroll
        for (int k = 0; k < 16; k++) {
            float a[8], bb[8];
            *(float4*)(a)      = *(const float4*)&As[cur][k][ty * 8];
            *(float4*)(a + 4)  = *(const float4*)&As[cur][k][ty * 8 + 4];
            *(float4*)(bb)     = *(const float4*)&Bs[cur][k][tx * 8];
            *(float4*)(bb + 4) = *(const float4*)&Bs[cur][k][tx * 8 + 4];
#pragma unroll
            for (int i = 0; i < 8; i++)
#pragma unroll
                for (int j = 0; j < 8; j++)
                    acc[i][j] = fmaf(a[i], bb[j], acc[i][j]);
        }
        if (kt + 1 < NK) {
            const int nxt = cur ^ 1;
            *(float4*)&As[nxt][kr0][cq0] = a0;
            *(float4*)&As[nxt][kr1][cq0] = a1;
            *(float4*)&Bs[nxt][kr0][cq0] = b0;
            *(float4*)&Bs[nxt][kr1][cq0] = b1;
        }
        __syncthreads();
    }

    float* C = g_P + ((size_t)(s * BB + b)) * DM * DM;
#pragma unroll
    for (int i = 0; i < 8; i++) {
        float* crow = C + (size_t)(ti * 128 + ty * 8 + i) * DM + tj * 128 + tx * 8;
        *(float4*)(crow)     = make_float4(acc[i][0], acc[i][1], acc[i][2], acc[i][3]);
        *(float4*)(crow + 4) = make_float4(acc[i][4], acc[i][5], acc[i][6], acc[i][7]);
    }
}

__global__ void reduce_g_kernel()
{
    const int idx = blockIdx.x * 256 + threadIdx.x;
    const int b = idx >> 18;
    const int r = idx & (DM * DM - 1);
    const int i = r >> 9;
    const int j = r & 511;
    if (j < i) return;
    float s = 0.f;
#pragma unroll
    for (int sp = 0; sp < SPLITK; sp++)
        s += g_P[((size_t)(sp * BB + b)) * DM * DM + r];
    g_G[(size_t)b * DM * DM + (size_t)i * DM + j] = s;
    g_G[(size_t)b * DM * DM + (size_t)j * DM + i] = s;
}

// ============================================================================
// mean over n of X: float4 per thread, 32 chunks of 256 rows, unroll 4
// grid (BB, 1, MCH), 128 threads
// ============================================================================
__global__ void meanx1_kernel(const float* __restrict__ X)
{
    const int b  = blockIdx.x;
    const int ch = blockIdx.z;
    const int j  = threadIdx.x * 4;
    const float* base = X + ((size_t)b * NSEQ + (size_t)ch * 256) * DM + j;
    float4 s0 = make_float4(0.f, 0.f, 0.f, 0.f);
    float4 s1 = s0, s2 = s0, s3 = s0;
    for (int i = 0; i < 256; i += 4) {
        float4 v0 = *(const float4*)(base + (size_t)(i + 0) * DM);
        float4 v1 = *(const float4*)(base + (size_t)(i + 1) * DM);
        float4 v2 = *(const float4*)(base + (size_t)(i + 2) * DM);
        float4 v3 = *(const float4*)(base + (size_t)(i + 3) * DM);
        s0.x += v0.x; s0.y += v0.y; s0.z += v0.z; s0.w += v0.w;
        s1.x += v1.x; s1.y += v1.y; s1.z += v1.z; s1.w += v1.w;
        s2.x += v2.x; s2.y += v2.y; s2.z += v2.z; s2.w += v2.w;
        s3.x += v3.x; s3.y += v3.y; s3.z += v3.z; s3.w += v3.w;
    }
    float4 r = make_float4((s0.x + s1.x) + (s2.x + s3.x),
                           (s0.y + s1.y) + (s2.y + s3.y),
                           (s0.z + s1.z) + (s2.z + s3.z),
                           (s0.w + s1.w) + (s2.w + s3.w));
    *(float4*)(g_Pm + (b * MCH + ch) * DM + j) = r;
}

__global__ void meanx2_kernel()
{
    const int b = blockIdx.x;
    const int j = blockIdx.y * 128 + threadIdx.x;
    float s = 0.f;
#pragma unroll
    for (int c = 0; c < MCH; c++) s += g_Pm[(b * MCH + c) * DM + j];
    g_xm[b * DM + j] = s * (1.0f / (float)NSEQ);
}

__global__ void first_kernel(const float* __restrict__ Wv)
{
    const int b    = blockIdx.x;
    const int j    = blockIdx.y * 8 + (threadIdx.x >> 5);
    const int lane = threadIdx.x & 31;
    const float* xm = g_xm + b * DM;
    const float* w  = Wv + (size_t)j * DM;
    float s = 0.f;
    for (int k = lane; k < DM; k += 32) s += xm[k] * w[k];
#pragma unroll
    for (int o = 16; o; o >>= 1) s += __shfl_xor_sync(0xFFFFFFFFu, s, o);
    if (lane == 0) g_first[b * DM + j] = s;
}

// ============================================================================
// small batched 512^3 GEMM. mode 0: M1[b] = Wv @ G[b] (NN, fp32 out).
// mode 1: KVt[b] = M1[b] @ Wtheta^T (NT) -> fp16 output.
// (KV^T = Wv G Wtheta^T since G is symmetric.)
// ============================================================================
__global__ void __launch_bounds__(128) small_gemm_kernel(
    const float* __restrict__ W, int mode)
{
    __shared__ float As[16][68];
    __shared__ float Bs[16][68];
    const int tid = threadIdx.x;
    const int i0  = blockIdx.x * 64;
    const int j0  = blockIdx.y * 64;
    const int b   = blockIdx.z;
    const size_t bo = (size_t)b * DM * DM;
    const float* __restrict__ A = (mode == 0) ? W : (g_M1 + bo);
    const float* __restrict__ B = (mode == 0) ? (g_G + bo) : W;
    const int transB = mode;

    const int tx = tid & 15;
    const int ty = tid >> 4;
    const int r0  = tid >> 2;
    const int r1  = r0 + 32;
    const int kq0 = (tid & 3) << 2;
    const int kr0 = tid >> 4;
    const int kr1 = kr0 + 8;
    const int cq0 = (tid & 15) << 2;

    float acc[8][4];
#pragma unroll
    for (int i = 0; i < 8; i++)
#pragma unroll
        for (int j = 0; j < 4; j++) acc[i][j] = 0.f;

    for (int k0 = 0; k0 < DM; k0 += 16) {
        float4 va0 = *(const float4*)(A + (size_t)(i0 + r0) * DM + k0 + kq0);
        float4 va1 = *(const float4*)(A + (size_t)(i0 + r1) * DM + k0 + kq0);
        As[kq0 + 0][r0] = va0.x; As[kq0 + 1][r0] = va0.y;
        As[kq0 + 2][r0] = va0.z; As[kq0 + 3][r0] = va0.w;
        As[kq0 + 0][r1] = va1.x; As[kq0 + 1][r1] = va1.y;
        As[kq0 + 2][r1] = va1.z; As[kq0 + 3][r1] = va1.w;
        if (transB) {
            float4 vb0 = *(const float4*)(B + (size_t)(j0 + r0) * DM + k0 + kq0);
            float4 vb1 = *(const float4*)(B + (size_t)(j0 + r1) * DM + k0 + kq0);
            Bs[kq0 + 0][r0] = vb0.x; Bs[kq0 + 1][r0] = vb0.y;
            Bs[kq0 + 2][r0] = vb0.z; Bs[kq0 + 3][r0] = vb0.w;
            Bs[kq0 + 0][r1] = vb1.x; Bs[kq0 + 1][r1] = vb1.y;
            Bs[kq0 + 2][r1] = vb1.z; Bs[kq0 + 3][r1] = vb1.w;
        } else {
            float4 vb0 = *(const float4*)(B + (size_t)(k0 + kr0) * DM + j0 + cq0);
            float4 vb1 = *(const float4*)(B + (size_t)(k0 + kr1) * DM + j0 + cq0);
            *(float4*)&Bs[kr0][cq0] = vb0;
            *(float4*)&Bs[kr1][cq0] = vb1;
        }
        __syncthreads();
#pragma unroll
        for (int k = 0; k < 16; k++) {
            float a[8], bb[4];
            *(float4*)(a)     = *(const float4*)&As[k][ty * 8];
            *(float4*)(a + 4) = *(const float4*)&As[k][ty * 8 + 4];
            *(float4*)(bb)    = *(const float4*)&Bs[k][tx * 4];
#pragma unroll
            for (int i = 0; i < 8; i++)
#pragma unroll
                for (int j = 0; j < 4; j++)
                    acc[i][j] = fmaf(a[i], bb[j], acc[i][j]);
        }
        __syncthreads();
    }

    if (mode == 0) {
#pragma unroll
        for (int i = 0; i < 8; i++)
            *(float4*)(g_M1 + bo + (size_t)(i0 + ty * 8 + i) * DM + j0 + tx * 4) =
                make_float4(acc[i][0], acc[i][1], acc[i][2], acc[i][3]);
    } else {
#pragma unroll
        for (int i = 0; i < 8; i++) {
            size_t o = bo + (size_t)(i0 + ty * 8 + i) * DM + j0 + tx * 4;
#pragma unroll
            for (int j = 0; j < 4; j++)
                g_KVh[o + j] = __float2half_rn(acc[i][j]);
        }
    }
}

// ============================================================================
// final GEMM, single-pass fp16 HMMA (mma.sync m16n8k16 f16, base PTX ISA):
//   out[m,j] = first[b][j] + scale * sum_k Xh[m,k] KVh[k,j]
// CTA 128x128, 8 warps (2x4), warp tile 64x32. K-chunks of 64, cp.async
// double-buffered smem (2 x 32 KB), SW128 swizzle.
// grid (DM/128, MTOT/128) — n fastest so CTAs sharing an X strip are adjacent.
// ============================================================================
#define SM_A 0                    // 2 bufs x 16384
#define SM_B 32768                // 2 bufs x 16384
#define FIN_SMEM 65536

__global__ void __launch_bounds__(256, 2) final_mma_kernel(float* __restrict__ out)
{
    extern __shared__ char smem[];
    const uint32_t sb = smem_to_u32(smem);
    const int tid  = threadIdx.x;
    const int wid  = tid >> 5;
    const int lane = tid & 31;
    const int wm   = wid >> 2;          // 0..1 (64-row halves)
    const int wn   = wid & 3;           // 0..3 (32-col quarters)
    const int n0   = blockIdx.x * 128;
    const int m0   = blockIdx.y * 128;
    const int b    = m0 / NSEQ;
    const size_t kvb = (size_t)b * DM * DM;

    // ldmatrix per-lane row/byte components (validated in round 8)
    const int a_row = wm * 64 + ((lane >> 3) & 1) * 8 + (lane & 7);
    const int a_byt = ((lane >> 4) & 1) * 16;
    const int b_row = wn * 32 + ((lane >> 4) & 1) * 8 + (lane & 7);
    const int b_byt = ((lane >> 3) & 1) * 16;

    // per-thread cp.async slots: 8 slots (4 A + 4 B)
    // slot i in [tid..2048 step 256]: arr = i>>10, idx = i&1023
    float acc[4][4][4];
#pragma unroll
    for (int mt = 0; mt < 4; mt++)
#pragma unroll
        for (int nt = 0; nt < 4; nt++)
#pragma unroll
            for (int q = 0; q < 4; q++) acc[mt][nt][q] = 0.f;

    // ---- stage helper (inlined twice via macro) ----
#define STAGE(kc, buf) do { \
        _Pragma("unroll") \
        for (int i = tid; i < 2048; i += 256) { \
            const int arr = i >> 10; \
            const int idx = i & 1023; \
            const int row = idx >> 3; \
            const int cg  = idx & 7; \
            const uint32_t sw = SW128((uint32_t)(row * 128 + cg * 16)); \
            const uint32_t dst = sb + (arr ? SM_B : SM_A) + (buf) * 16384 + sw; \
            const __half* src = arr \
                ? (g_KVh + kvb + (size_t)(n0 + row) * DM + (kc) * 64 + cg * 8) \
                : (g_Xh  + (size_t)(m0 + row) * DM + (kc) * 64 + cg * 8); \
            cp_async16(dst, src); \
        } \
        CP_COMMIT(); \
    } while (0)

    STAGE(0, 0);

    for (int kc = 0; kc < 8; kc++) {
        const int cur = kc & 1;
        if (kc + 1 < 8) {
            STAGE(kc + 1, cur ^ 1);
            CP_WAIT(1);
        } else {
            CP_WAIT(0);
        }
        __syncthreads();

        const uint32_t abase = sb + SM_A + cur * 16384;
        const uint32_t bbase = sb + SM_B + cur * 16384;
#pragma unroll
        for (int kk = 0; kk < 4; kk++) {
            uint32_t a[4][4], bb[4][2];
#pragma unroll
            for (int mt = 0; mt < 4; mt++) {
                uint32_t off = (uint32_t)((a_row + mt * 16) * 128 + kk * 32 + a_byt);
                ldmx4(a[mt], abase + SW128(off));
            }
#pragma unroll
            for (int p = 0; p < 2; p++) {
                uint32_t off = (uint32_t)((b_row + p * 16) * 128 + kk * 32 + b_byt);
                uint32_t r[4];
                ldmx4(r, bbase + SW128(off));
                bb[p * 2][0] = r[0]; bb[p * 2][1] = r[1];
                bb[p * 2 + 1][0] = r[2]; bb[p * 2 + 1][1] = r[3];
            }
#pragma unroll
            for (int mt = 0; mt < 4; mt++)
#pragma unroll
                for (int nt = 0; nt < 4; nt++)
                    mma16816(acc[mt][nt], a[mt], bb[nt]);
        }
        __syncthreads();   // protect cur buffer before it is refilled
    }

    // epilogue: c0,c1 -> row g, cols 2t,2t+1; c2,c3 -> row g+8
    const float scale = 1.0f / (8192.0f * sqrtf(512.0f));
    const int g = lane >> 2;
    const int t = lane & 3;
#pragma unroll
    for (int mt = 0; mt < 4; mt++) {
        const int r = m0 + wm * 64 + mt * 16 + g;
#pragma unroll
        for (int nt = 0; nt < 4; nt++) {
            const int c = n0 + wn * 32 + nt * 8 + t * 2;
            const float f0 = g_first[b * DM + c];
            const float f1 = g_first[b * DM + c + 1];
            *(float2*)(out + (size_t)r * DM + c) =
                make_float2(f0 + scale * acc[mt][nt][0],
                            f1 + scale * acc[mt][nt][1]);
            *(float2*)(out + (size_t)(r + 8) * DM + c) =
                make_float2(f0 + scale * acc[mt][nt][2],
                            f1 + scale * acc[mt][nt][3]);
        }
    }
#undef STAGE
}

// ============================================================================
extern "C" void kernel_launch(void* const* d_in, const int* in_sizes, int n_in,
                              void* d_out, int out_size)
{
    (void)in_sizes; (void)n_in; (void)out_size;
    const float* X  = (const float*)d_in[0];
    const float* Wv = (const float*)d_in[1];
    const float* Wt = (const float*)d_in[2];
    float* out = (float*)d_out;

    cudaFuncSetAttribute(final_mma_kernel,
                         cudaFuncAttributeMaxDynamicSharedMemorySize, FIN_SMEM);

    // 0) fp16 conversion of X
    convert_x_kernel<<<dim3((MTOT * DM) / (256 * 8)), 256>>>(X);
    // 1) G[b] = X[b]^T X[b]  (fp32, split-K, upper-triangle)
    xtx_kernel<<<dim3(10, BB * SPLITK), 256>>>(X);
    // 2) mean over n of X, then first = mean(X) @ Wv^T
    meanx1_kernel<<<dim3(BB, 1, MCH), 128>>>(X);
    meanx2_kernel<<<dim3(BB, 4), 128>>>();
    first_kernel<<<dim3(BB, 64), 256>>>(Wv);
    // 3) reduce + mirror G
    reduce_g_kernel<<<dim3((BB * DM * DM) / 256), 256>>>();
    // 4) M1[b] = Wv @ G[b]; KVt[b] = M1[b] @ Wtheta^T (fp16 out)
    small_gemm_kernel<<<dim3(8, 8, BB), 128>>>(Wv, 0);
    small_gemm_kernel<<<dim3(8, 8, BB), 128>>>(Wt, 1);
    // 5) out = first + scale * X @ KV   (single-pass fp16 HMMA)
    final_mma_kernel<<<dim3(DM / 128, MTOT / 128), 256, FIN_SMEM>>>(out);
}

// round 10
// speedup vs baseline: 2.8086x; 1.5842x over previous
#include <cuda_runtime.h>
#include <cuda_fp16.h>
#include <math.h>
#include <stdint.h>

#define BB     4
#define NSEQ   8192
#define DM     512
#define MTOT   (BB * NSEQ)       // 32768
#define SPLITK 32
#define KC     (NSEQ / SPLITK)   // 256
#define MCH    32                // meanx chunks

// ---------------- scratch (static device memory; referenced ONLY from device
// code — host-side use of these symbols silently hits host memory via ATS) ---
__device__ float g_P [SPLITK * BB * DM * DM];   // X^T X split-K partials
__device__ float g_G [BB * DM * DM];            // X^T X
__device__ float g_M1[BB * DM * DM];            // Wv @ G
__device__ float g_Pm[BB * MCH * DM];
__device__ float g_xm[BB * DM];
__device__ float g_first[BB * DM];
__device__ __half g_Xh [(size_t)MTOT * DM];     // fp16 X       [b*n][d]
__device__ __half g_Xt [(size_t)BB * DM * NSEQ];// fp16 X^T     [b][d][n]
__device__ __half g_KVh[BB * DM * DM];          // fp16 KV^T    [j][k]

__constant__ int c_ti[10] = {0,0,0,0,1,1,1,2,2,3};
__constant__ int c_tj[10] = {0,1,2,3,1,2,3,2,3,3};

#define SW128(x) ((x) ^ (((x) >> 3) & 0x70))

__device__ __forceinline__ uint32_t smem_to_u32(const void* p) {
    uint32_t a;
    asm("{ .reg .u64 t; cvta.to.shared.u64 t, %1; cvt.u32.u64 %0, t; }"
        : "=r"(a) : "l"(p));
    return a;
}
__device__ __forceinline__ void ldmx4(uint32_t r[4], uint32_t addr) {
    asm volatile("ldmatrix.sync.aligned.m8n8.x4.shared.b16 {%0,%1,%2,%3}, [%4];"
        : "=r"(r[0]), "=r"(r[1]), "=r"(r[2]), "=r"(r[3]) : "r"(addr));
}
__device__ __forceinline__ void mma16816(float c[4], const uint32_t a[4],
                                         const uint32_t b[2]) {
    asm volatile("mma.sync.aligned.m16n8k16.row.col.f32.f16.f16.f32 "
        "{%0,%1,%2,%3}, {%4,%5,%6,%7}, {%8,%9}, {%0,%1,%2,%3};"
        : "+f"(c[0]), "+f"(c[1]), "+f"(c[2]), "+f"(c[3])
        : "r"(a[0]), "r"(a[1]), "r"(a[2]), "r"(a[3]), "r"(b[0]), "r"(b[1]));
}
__device__ __forceinline__ void cp_async16(uint32_t dst, const void* src) {
    asm volatile("cp.async.cg.shared.global [%0], [%1], 16;"
        :: "r"(dst), "l"(src) : "memory");
}
#define CP_COMMIT() asm volatile("cp.async.commit_group;" ::: "memory")
#define CP_WAIT(n)  asm volatile("cp.async.wait_group %0;" :: "n"(n) : "memory")

// ============================================================================
// fp16 conversion of X + fused transpose: g_Xh [n][d] and g_Xt [d][n].
// grid (NSEQ/64, DM/64, BB), 256 threads, 64x64 tiles via smem.
// ============================================================================
__global__ void convert_x_kernel(const float* __restrict__ X)
{
    __shared__ __half s[64][72];
    const int b  = blockIdx.z;
    const int n0 = blockIdx.x * 64;
    const int d0 = blockIdx.y * 64;
    const int t  = threadIdx.x;
    for (int i = t; i < 1024; i += 256) {
        const int row = i >> 4;          // n-local
        const int cq  = (i & 15) << 2;   // d-local
        float4 v = *(const float4*)(X + ((size_t)b * NSEQ + n0 + row) * DM + d0 + cq);
        __half h0 = __float2half_rn(v.x), h1 = __float2half_rn(v.y);
        __half h2 = __float2half_rn(v.z), h3 = __float2half_rn(v.w);
        uint2 u; __half* ph = (__half*)&u;
        ph[0] = h0; ph[1] = h1; ph[2] = h2; ph[3] = h3;
        *(uint2*)(g_Xh + ((size_t)b * NSEQ + n0 + row) * DM + d0 + cq) = u;
        s[cq + 0][row] = h0; s[cq + 1][row] = h1;
        s[cq + 2][row] = h2; s[cq + 3][row] = h3;
    }
    __syncthreads();
    for (int i = t; i < 1024; i += 256) {
        const int dr = i >> 4;           // d-local
        const int nq = (i & 15) << 2;    // n-local
        uint2 u; __half* ph = (__half*)&u;
        ph[0] = s[dr][nq]; ph[1] = s[dr][nq + 1];
        ph[2] = s[dr][nq + 2]; ph[3] = s[dr][nq + 3];
        *(uint2*)(g_Xt + ((size_t)b * DM + d0 + dr) * NSEQ + n0 + nq) = u;
    }
}

// ============================================================================
// X^T X on fp16 HMMA (same NT template as final_mma, validated round 9):
//   P[s][b][i][j] = sum_{k in chunk s} Xt[b,i,k] * Xt[b,j,k]
// A = Xt rows ti*128.., B = Xt rows tj*128.., K = 256 (4 chunks of 64).
// grid (10, BB*SPLITK), 256 threads, cp.async double-buffered, SW128.
// ============================================================================
#define SM_A 0                    // 2 bufs x 16384
#define SM_B 32768                // 2 bufs x 16384
#define MMA_SMEM 65536

__global__ void __launch_bounds__(256, 2) xtx_mma_kernel()
{
    extern __shared__ char smem[];
    const uint32_t sb = smem_to_u32(smem);
    const int tid  = threadIdx.x;
    const int wid  = tid >> 5;
    const int lane = tid & 31;
    const int wm   = wid >> 2;
    const int wn   = wid & 3;
    const int ti   = c_ti[blockIdx.x];
    const int tj   = c_tj[blockIdx.x];
    const int b    = blockIdx.y / SPLITK;
    const int s    = blockIdx.y % SPLITK;
    const __half* __restrict__ Abase =
        g_Xt + ((size_t)b * DM + ti * 128) * NSEQ + (size_t)s * KC;
    const __half* __restrict__ Bbase =
        g_Xt + ((size_t)b * DM + tj * 128) * NSEQ + (size_t)s * KC;

    const int a_row = wm * 64 + ((lane >> 3) & 1) * 8 + (lane & 7);
    const int a_byt = ((lane >> 4) & 1) * 16;
    const int b_row = wn * 32 + ((lane >> 4) & 1) * 8 + (lane & 7);
    const int b_byt = ((lane >> 3) & 1) * 16;

    float acc[4][4][4];
#pragma unroll
    for (int mt = 0; mt < 4; mt++)
#pragma unroll
        for (int nt = 0; nt < 4; nt++)
#pragma unroll
            for (int q = 0; q < 4; q++) acc[mt][nt][q] = 0.f;

#define XSTAGE(kc, buf) do { \
        _Pragma("unroll") \
        for (int i = tid; i < 2048; i += 256) { \
            const int arr = i >> 10; \
            const int idx = i & 1023; \
            const int row = idx >> 3; \
            const int cg  = idx & 7; \
            const uint32_t sw = SW128((uint32_t)(row * 128 + cg * 16)); \
            const uint32_t dst = sb + (arr ? SM_B : SM_A) + (buf) * 16384 + sw; \
            const __half* src = (arr ? Bbase : Abase) \
                + (size_t)row * NSEQ + (kc) * 64 + cg * 8; \
            cp_async16(dst, src); \
        } \
        CP_COMMIT(); \
    } while (0)

    XSTAGE(0, 0);

    const int NCH = KC / 64;     // 4
    for (int kc = 0; kc < NCH; kc++) {
        const int cur = kc & 1;
        if (kc + 1 < NCH) {
            XSTAGE(kc + 1, cur ^ 1);
            CP_WAIT(1);
        } else {
            CP_WAIT(0);
        }
        __syncthreads();

        const uint32_t abase = sb + SM_A + cur * 16384;
        const uint32_t bbase = sb + SM_B + cur * 16384;
#pragma unroll
        for (int kk = 0; kk < 4; kk++) {
            uint32_t a[4][4], bb[4][2];
#pragma unroll
            for (int mt = 0; mt < 4; mt++) {
                uint32_t off = (uint32_t)((a_row + mt * 16) * 128 + kk * 32 + a_byt);
                ldmx4(a[mt], abase + SW128(off));
            }
#pragma unroll
            for (int p = 0; p < 2; p++) {
                uint32_t off = (uint32_t)((b_row + p * 16) * 128 + kk * 32 + b_byt);
                uint32_t r[4];
                ldmx4(r, bbase + SW128(off));
                bb[p * 2][0] = r[0]; bb[p * 2][1] = r[1];
                bb[p * 2 + 1][0] = r[2]; bb[p * 2 + 1][1] = r[3];
            }
#pragma unroll
            for (int mt = 0; mt < 4; mt++)
#pragma unroll
                for (int nt = 0; nt < 4; nt++)
                    mma16816(acc[mt][nt], a[mt], bb[nt]);
        }
        __syncthreads();
    }
#undef XSTAGE

    // epilogue: raw fp32 partials into g_P (same layout as before)
    float* C = g_P + ((size_t)(s * BB + b)) * DM * DM;
    const int g = lane >> 2;
    const int t = lane & 3;
#pragma unroll
    for (int mt = 0; mt < 4; mt++) {
        const int r = ti * 128 + wm * 64 + mt * 16 + g;
#pragma unroll
        for (int nt = 0; nt < 4; nt++) {
            const int c = tj * 128 + wn * 32 + nt * 8 + t * 2;
            *(float2*)(C + (size_t)r * DM + c) =
                make_float2(acc[mt][nt][0], acc[mt][nt][1]);
            *(float2*)(C + (size_t)(r + 8) * DM + c) =
                make_float2(acc[mt][nt][2], acc[mt][nt][3]);
        }
    }
}

__global__ void reduce_g_kernel()
{
    const int idx = blockIdx.x * 256 + threadIdx.x;
    const int b = idx >> 18;
    const int r = idx & (DM * DM - 1);
    const int i = r >> 9;
    const int j = r & 511;
    if (j < i) return;
    float s = 0.f;
#pragma unroll
    for (int sp = 0; sp < SPLITK; sp++)
        s += g_P[((size_t)(sp * BB + b)) * DM * DM + r];
    g_G[(size_t)b * DM * DM + (size_t)i * DM + j] = s;
    g_G[(size_t)b * DM * DM + (size_t)j * DM + i] = s;
}

// ============================================================================
// mean over n of X: float4 per thread, 32 chunks of 256 rows, unroll 4
// ============================================================================
__global__ void meanx1_kernel(const float* __restrict__ X)
{
    const int b  = blockIdx.x;
    const int ch = blockIdx.z;
    const int j  = threadIdx.x * 4;
    const float* base = X + ((size_t)b * NSEQ + (size_t)ch * 256) * DM + j;
    float4 s0 = make_float4(0.f, 0.f, 0.f, 0.f);
    float4 s1 = s0, s2 = s0, s3 = s0;
    for (int i = 0; i < 256; i += 4) {
        float4 v0 = *(const float4*)(base + (size_t)(i + 0) * DM);
        float4 v1 = *(const float4*)(base + (size_t)(i + 1) * DM);
        float4 v2 = *(const float4*)(base + (size_t)(i + 2) * DM);
        float4 v3 = *(const float4*)(base + (size_t)(i + 3) * DM);
        s0.x += v0.x; s0.y += v0.y; s0.z += v0.z; s0.w += v0.w;
        s1.x += v1.x; s1.y += v1.y; s1.z += v1.z; s1.w += v1.w;
        s2.x += v2.x; s2.y += v2.y; s2.z += v2.z; s2.w += v2.w;
        s3.x += v3.x; s3.y += v3.y; s3.z += v3.z; s3.w += v3.w;
    }
    float4 r = make_float4((s0.x + s1.x) + (s2.x + s3.x),
                           (s0.y + s1.y) + (s2.y + s3.y),
                           (s0.z + s1.z) + (s2.z + s3.z),
                           (s0.w + s1.w) + (s2.w + s3.w));
    *(float4*)(g_Pm + (b * MCH + ch) * DM + j) = r;
}

__global__ void meanx2_kernel()
{
    const int b = blockIdx.x;
    const int j = blockIdx.y * 128 + threadIdx.x;
    float s = 0.f;
#pragma unroll
    for (int c = 0; c < MCH; c++) s += g_Pm[(b * MCH + c) * DM + j];
    g_xm[b * DM + j] = s * (1.0f / (float)NSEQ);
}

__global__ void first_kernel(const float* __restrict__ Wv)
{
    const int b    = blockIdx.x;
    const int j    = blockIdx.y * 8 + (threadIdx.x >> 5);
    const int lane = threadIdx.x & 31;
    const float* xm = g_xm + b * DM;
    const float* w  = Wv + (size_t)j * DM;
    float s = 0.f;
    for (int k = lane; k < DM; k += 32) s += xm[k] * w[k];
#pragma unroll
    for (int o = 16; o; o >>= 1) s += __shfl_xor_sync(0xFFFFFFFFu, s, o);
    if (lane == 0) g_first[b * DM + j] = s;
}

// ============================================================================
// small batched 512^3 GEMM. mode 0: M1[b] = Wv @ G[b] (NN, fp32 out).
// mode 1: KVt[b] = M1[b] @ Wtheta^T (NT) -> fp16 output.
// ============================================================================
__global__ void __launch_bounds__(128) small_gemm_kernel(
    const float* __restrict__ W, int mode)
{
    __shared__ float As[16][68];
    __shared__ float Bs[16][68];
    const int tid = threadIdx.x;
    const int i0  = blockIdx.x * 64;
    const int j0  = blockIdx.y * 64;
    const int b   = blockIdx.z;
    const size_t bo = (size_t)b * DM * DM;
    const float* __restrict__ A = (mode == 0) ? W : (g_M1 + bo);
    const float* __restrict__ B = (mode == 0) ? (g_G + bo) : W;
    const int transB = mode;

    const int tx = tid & 15;
    const int ty = tid >> 4;
    const int r0  = tid >> 2;
    const int r1  = r0 + 32;
    const int kq0 = (tid & 3) << 2;
    const int kr0 = tid >> 4;
    const int kr1 = kr0 + 8;
    const int cq0 = (tid & 15) << 2;

    float acc[8][4];
#pragma unroll
    for (int i = 0; i < 8; i++)
#pragma unroll
        for (int j = 0; j < 4; j++) acc[i][j] = 0.f;

    for (int k0 = 0; k0 < DM; k0 += 16) {
        float4 va0 = *(const float4*)(A + (size_t)(i0 + r0) * DM + k0 + kq0);
        float4 va1 = *(const float4*)(A + (size_t)(i0 + r1) * DM + k0 + kq0);
        As[kq0 + 0][r0] = va0.x; As[kq0 + 1][r0] = va0.y;
        As[kq0 + 2][r0] = va0.z; As[kq0 + 3][r0] = va0.w;
        As[kq0 + 0][r1] = va1.x; As[kq0 + 1][r1] = va1.y;
        As[kq0 + 2][r1] = va1.z; As[kq0 + 3][r1] = va1.w;
        if (transB) {
            float4 vb0 = *(const float4*)(B + (size_t)(j0 + r0) * DM + k0 + kq0);
            float4 vb1 = *(const float4*)(B + (size_t)(j0 + r1) * DM + k0 + kq0);
            Bs[kq0 + 0][r0] = vb0.x; Bs[kq0 + 1][r0] = vb0.y;
            Bs[kq0 + 2][r0] = vb0.z; Bs[kq0 + 3][r0] = vb0.w;
            Bs[kq0 + 0][r1] = vb1.x; Bs[kq0 + 1][r1] = vb1.y;
            Bs[kq0 + 2][r1] = vb1.z; Bs[kq0 + 3][r1] = vb1.w;
        } else {
            float4 vb0 = *(const float4*)(B + (size_t)(k0 + kr0) * DM + j0 + cq0);
            float4 vb1 = *(const float4*)(B + (size_t)(k0 + kr1) * DM + j0 + cq0);
            *(float4*)&Bs[kr0][cq0] = vb0;
            *(float4*)&Bs[kr1][cq0] = vb1;
        }
        __syncthreads();
#pragma unroll
        for (int k = 0; k < 16; k++) {
            float a[8], bb[4];
            *(float4*)(a)     = *(const float4*)&As[k][ty * 8];
            *(float4*)(a + 4) = *(const float4*)&As[k][ty * 8 + 4];
            *(float4*)(bb)    = *(const float4*)&Bs[k][tx * 4];
#pragma unroll
            for (int i = 0; i < 8; i++)
#pragma unroll
                for (int j = 0; j < 4; j++)
                    acc[i][j] = fmaf(a[i], bb[j], acc[i][j]);
        }
        __syncthreads();
    }

    if (mode == 0) {
#pragma unroll
        for (int i = 0; i < 8; i++)
            *(float4*)(g_M1 + bo + (size_t)(i0 + ty * 8 + i) * DM + j0 + tx * 4) =
                make_float4(acc[i][0], acc[i][1], acc[i][2], acc[i][3]);
    } else {
#pragma unroll
        for (int i = 0; i < 8; i++) {
            size_t o = bo + (size_t)(i0 + ty * 8 + i) * DM + j0 + tx * 4;
#pragma unroll
            for (int j = 0; j < 4; j++)
                g_KVh[o + j] = __float2half_rn(acc[i][j]);
        }
    }
}

// ============================================================================
// final GEMM, single-pass fp16 HMMA (validated round 9):
//   out[m,j] = first[b][j] + scale * sum_k Xh[m,k] KVh[k,j]
// ============================================================================
__global__ void __launch_bounds__(256, 2) final_mma_kernel(float* __restrict__ out)
{
    extern __shared__ char smem[];
    const uint32_t sb = smem_to_u32(smem);
    const int tid  = threadIdx.x;
    const int wid  = tid >> 5;
    const int lane = tid & 31;
    const int wm   = wid >> 2;
    const int wn   = wid & 3;
    const int n0   = blockIdx.x * 128;
    const int m0   = blockIdx.y * 128;
    const int b    = m0 / NSEQ;
    const size_t kvb = (size_t)b * DM * DM;

    const int a_row = wm * 64 + ((lane >> 3) & 1) * 8 + (lane & 7);
    const int a_byt = ((lane >> 4) & 1) * 16;
    const int b_row = wn * 32 + ((lane >> 4) & 1) * 8 + (lane & 7);
    const int b_byt = ((lane >> 3) & 1) * 16;

    float acc[4][4][4];
#pragma unroll
    for (int mt = 0; mt < 4; mt++)
#pragma unroll
        for (int nt = 0; nt < 4; nt++)
#pragma unroll
            for (int q = 0; q < 4; q++) acc[mt][nt][q] = 0.f;

#define STAGE(kc, buf) do { \
        _Pragma("unroll") \
        for (int i = tid; i < 2048; i += 256) { \
            const int arr = i >> 10; \
            const int idx = i & 1023; \
            const int row = idx >> 3; \
            const int cg  = idx & 7; \
            const uint32_t sw = SW128((uint32_t)(row * 128 + cg * 16)); \
            const uint32_t dst = sb + (arr ? SM_B : SM_A) + (buf) * 16384 + sw; \
            const __half* src = arr \
                ? (g_KVh + kvb + (size_t)(n0 + row) * DM + (kc) * 64 + cg * 8) \
                : (g_Xh  + (size_t)(m0 + row) * DM + (kc) * 64 + cg * 8); \
            cp_async16(dst, src); \
        } \
        CP_COMMIT(); \
    } while (0)

    STAGE(0, 0);

    for (int kc = 0; kc < 8; kc++) {
        const int cur = kc & 1;
        if (kc + 1 < 8) {
            STAGE(kc + 1, cur ^ 1);
            CP_WAIT(1);
        } else {
            CP_WAIT(0);
        }
        __syncthreads();

        const uint32_t abase = sb + SM_A + cur * 16384;
        const uint32_t bbase = sb + SM_B + cur * 16384;
#pragma unroll
        for (int kk = 0; kk < 4; kk++) {
            uint32_t a[4][4], bb[4][2];
#pragma unroll
            for (int mt = 0; mt < 4; mt++) {
                uint32_t off = (uint32_t)((a_row + mt * 16) * 128 + kk * 32 + a_byt);
                ldmx4(a[mt], abase + SW128(off));
            }
#pragma unroll
            for (int p = 0; p < 2; p++) {
                uint32_t off = (uint32_t)((b_row + p * 16) * 128 + kk * 32 + b_byt);
                uint32_t r[4];
                ldmx4(r, bbase + SW128(off));
                bb[p * 2][0] = r[0]; bb[p * 2][1] = r[1];
                bb[p * 2 + 1][0] = r[2]; bb[p * 2 + 1][1] = r[3];
            }
#pragma unroll
            for (int mt = 0; mt < 4; mt++)
#pragma unroll
                for (int nt = 0; nt < 4; nt++)
                    mma16816(acc[mt][nt], a[mt], bb[nt]);
        }
        __syncthreads();
    }
#undef STAGE

    const float scale = 1.0f / (8192.0f * sqrtf(512.0f));
    const int g = lane >> 2;
    const int t = lane & 3;
#pragma unroll
    for (int mt = 0; mt < 4; mt++) {
        const int r = m0 + wm * 64 + mt * 16 + g;
#pragma unroll
        for (int nt = 0; nt < 4; nt++) {
            const int c = n0 + wn * 32 + nt * 8 + t * 2;
            const float f0 = g_first[b * DM + c];
            const float f1 = g_first[b * DM + c + 1];
            *(float2*)(out + (size_t)r * DM + c) =
                make_float2(f0 + scale * acc[mt][nt][0],
                            f1 + scale * acc[mt][nt][1]);
            *(float2*)(out + (size_t)(r + 8) * DM + c) =
                make_float2(f0 + scale * acc[mt][nt][2],
                            f1 + scale * acc[mt][nt][3]);
        }
    }
}

// ============================================================================
extern "C" void kernel_launch(void* const* d_in, const int* in_sizes, int n_in,
                              void* d_out, int out_size)
{
    (void)in_sizes; (void)n_in; (void)out_size;
    const float* X  = (const float*)d_in[0];
    const float* Wv = (const float*)d_in[1];
    const float* Wt = (const float*)d_in[2];
    float* out = (float*)d_out;

    cudaFuncSetAttribute(final_mma_kernel,
                         cudaFuncAttributeMaxDynamicSharedMemorySize, MMA_SMEM);
    cudaFuncSetAttribute(xtx_mma_kernel,
                         cudaFuncAttributeMaxDynamicSharedMemorySize, MMA_SMEM);

    // 0) fp16 conversion of X (+ fused transpose)
    convert_x_kernel<<<dim3(NSEQ / 64, DM / 64, BB), 256>>>(X);
    // 1) G[b] = X[b]^T X[b]  (fp16 HMMA, split-K, upper-triangle)
    xtx_mma_kernel<<<dim3(10, BB * SPLITK), 256, MMA_SMEM>>>();
    // 2) mean over n of X, then first = mean(X) @ Wv^T
    meanx1_kernel<<<dim3(BB, 1, MCH), 128>>>(X);
    meanx2_kernel<<<dim3(BB, 4), 128>>>();
    first_kernel<<<dim3(BB, 64), 256>>>(Wv);
    // 3) reduce + mirror G
    reduce_g_kernel<<<dim3((BB * DM * DM) / 256), 256>>>();
    // 4) M1[b] = Wv @ G[b]; KVt[b] = M1[b] @ Wtheta^T (fp16 out)
    small_gemm_kernel<<<dim3(8, 8, BB), 128>>>(Wv, 0);
    small_gemm_kernel<<<dim3(8, 8, BB), 128>>>(Wt, 1);
    // 5) out = first + scale * X @ KV   (single-pass fp16 HMMA)
    final_mma_kernel<<<dim3(DM / 128, MTOT / 128), 256, MMA_SMEM>>>(out);
}

// round 11
// speedup vs baseline: 3.2979x; 1.1742x over previous
#include <cuda_runtime.h>
#include <cuda_fp16.h>
#include <math.h>
#include <stdint.h>

#define BB     4
#define NSEQ   8192
#define DM     512
#define MTOT   (BB * NSEQ)       // 32768
#define SPLITK 16
#define KC     (NSEQ / SPLITK)   // 512
#define MCH    32                // meanx chunks

// ---------------- scratch (static device memory; referenced ONLY from device
// code — host-side use of these symbols silently hits host memory via ATS) ---
__device__ float g_P [SPLITK * BB * DM * DM];   // X^T X split-K partials
__device__ float g_Pm[BB * MCH * DM];
__device__ float g_first[BB * DM];
__device__ __half g_Xh [(size_t)MTOT * DM];     // fp16 X       [b*n][d]
__device__ __half g_Xt [(size_t)BB * DM * NSEQ];// fp16 X^T     [b][d][n]
__device__ __half g_Gh [BB * DM * DM];          // fp16 G = X^T X (symmetric)
__device__ __half g_M1h[BB * DM * DM];          // fp16 Wv @ G
__device__ __half g_KVh[BB * DM * DM];          // fp16 KV^T    [j][k]
__device__ __half g_Wvh[DM * DM];               // fp16 Wv
__device__ __half g_Wth[DM * DM];               // fp16 Wtheta

__constant__ int c_ti[10] = {0,0,0,0,1,1,1,2,2,3};
__constant__ int c_tj[10] = {0,1,2,3,1,2,3,2,3,3};

#define SW128(x) ((x) ^ (((x) >> 3) & 0x70))

__device__ __forceinline__ uint32_t smem_to_u32(const void* p) {
    uint32_t a;
    asm("{ .reg .u64 t; cvta.to.shared.u64 t, %1; cvt.u32.u64 %0, t; }"
        : "=r"(a) : "l"(p));
    return a;
}
__device__ __forceinline__ void ldmx4(uint32_t r[4], uint32_t addr) {
    asm volatile("ldmatrix.sync.aligned.m8n8.x4.shared.b16 {%0,%1,%2,%3}, [%4];"
        : "=r"(r[0]), "=r"(r[1]), "=r"(r[2]), "=r"(r[3]) : "r"(addr));
}
__device__ __forceinline__ void mma16816(float c[4], const uint32_t a[4],
                                         const uint32_t b[2]) {
    asm volatile("mma.sync.aligned.m16n8k16.row.col.f32.f16.f16.f32 "
        "{%0,%1,%2,%3}, {%4,%5,%6,%7}, {%8,%9}, {%0,%1,%2,%3};"
        : "+f"(c[0]), "+f"(c[1]), "+f"(c[2]), "+f"(c[3])
        : "r"(a[0]), "r"(a[1]), "r"(a[2]), "r"(a[3]), "r"(b[0]), "r"(b[1]));
}
__device__ __forceinline__ void cp_async16(uint32_t dst, const void* src) {
    asm volatile("cp.async.cg.shared.global [%0], [%1], 16;"
        :: "r"(dst), "l"(src) : "memory");
}
#define CP_COMMIT() asm volatile("cp.async.commit_group;" ::: "memory")
#define CP_WAIT(n)  asm volatile("cp.async.wait_group %0;" :: "n"(n) : "memory")

#define SM_A 0                    // 2 bufs x 16384
#define SM_B 32768                // 2 bufs x 16384
#define MMA_SMEM 65536

// generic NT stage: A rows (base + (r0+row)*stride), B rows (base + row*stride)
#define NT_STAGE(Abase, Bbase, stride, kc, buf) do { \
        _Pragma("unroll") \
        for (int i = tid; i < 2048; i += 256) { \
            const int arr = i >> 10; \
            const int idx = i & 1023; \
            const int row = idx >> 3; \
            const int cg  = idx & 7; \
            const uint32_t sw = SW128((uint32_t)(row * 128 + cg * 16)); \
            const uint32_t dst = sb + (arr ? SM_B : SM_A) + (buf) * 16384 + sw; \
            const __half* src = (arr ? (Bbase) : (Abase)) \
                + (size_t)row * (stride) + (kc) * 64 + cg * 8; \
            cp_async16(dst, src); \
        } \
        CP_COMMIT(); \
    } while (0)

// ============================================================================
// fp16 conversion of X + fused transpose: g_Xh [n][d] and g_Xt [d][n].
// grid (NSEQ/64, DM/64, BB), 256 threads, 64x64 tiles via smem.
// ============================================================================
__global__ void convert_x_kernel(const float* __restrict__ X)
{
    __shared__ __half s[64][72];
    const int b  = blockIdx.z;
    const int n0 = blockIdx.x * 64;
    const int d0 = blockIdx.y * 64;
    const int t  = threadIdx.x;
    for (int i = t; i < 1024; i += 256) {
        const int row = i >> 4;
        const int cq  = (i & 15) << 2;
        float4 v = *(const float4*)(X + ((size_t)b * NSEQ + n0 + row) * DM + d0 + cq);
        __half h0 = __float2half_rn(v.x), h1 = __float2half_rn(v.y);
        __half h2 = __float2half_rn(v.z), h3 = __float2half_rn(v.w);
        uint2 u; __half* ph = (__half*)&u;
        ph[0] = h0; ph[1] = h1; ph[2] = h2; ph[3] = h3;
        *(uint2*)(g_Xh + ((size_t)b * NSEQ + n0 + row) * DM + d0 + cq) = u;
        s[cq + 0][row] = h0; s[cq + 1][row] = h1;
        s[cq + 2][row] = h2; s[cq + 3][row] = h3;
    }
    __syncthreads();
    for (int i = t; i < 1024; i += 256) {
        const int dr = i >> 4;
        const int nq = (i & 15) << 2;
        uint2 u; __half* ph = (__half*)&u;
        ph[0] = s[dr][nq]; ph[1] = s[dr][nq + 1];
        ph[2] = s[dr][nq + 2]; ph[3] = s[dr][nq + 3];
        *(uint2*)(g_Xt + ((size_t)b * DM + d0 + dr) * NSEQ + n0 + nq) = u;
    }
}

// fp16 conversion of Wv / Wtheta. grid 256, 256 thr, 8 elems/thread.
__global__ void convert_w_kernel(const float* __restrict__ Wv,
                                 const float* __restrict__ Wt)
{
    const int blk = blockIdx.x;
    const float* src = (blk < 128) ? Wv : Wt;
    __half* dst = (blk < 128) ? g_Wvh : g_Wth;
    const size_t base = ((size_t)(blk & 127) * 256 + threadIdx.x) * 8;
    float4 v0 = *(const float4*)(src + base);
    float4 v1 = *(const float4*)(src + base + 4);
    uint4 u; __half* ph = (__half*)&u;
    ph[0] = __float2half_rn(v0.x); ph[1] = __float2half_rn(v0.y);
    ph[2] = __float2half_rn(v0.z); ph[3] = __float2half_rn(v0.w);
    ph[4] = __float2half_rn(v1.x); ph[5] = __float2half_rn(v1.y);
    ph[6] = __float2half_rn(v1.z); ph[7] = __float2half_rn(v1.w);
    *(uint4*)(dst + base) = u;
}

// ============================================================================
// X^T X on fp16 HMMA: P[s][b][i][j] = sum_{k in chunk s} Xt[b,i,k] Xt[b,j,k]
// grid (10, BB*SPLITK), 256 threads, K = 512 per CTA (8 chunks of 64).
// ============================================================================
__global__ void __launch_bounds__(256, 2) xtx_mma_kernel()
{
    extern __shared__ char smem[];
    const uint32_t sb = smem_to_u32(smem);
    const int tid  = threadIdx.x;
    const int wid  = tid >> 5;
    const int lane = tid & 31;
    const int wm   = wid >> 2;
    const int wn   = wid & 3;
    const int ti   = c_ti[blockIdx.x];
    const int tj   = c_tj[blockIdx.x];
    const int b    = blockIdx.y / SPLITK;
    const int s    = blockIdx.y % SPLITK;
    const __half* __restrict__ Abase =
        g_Xt + ((size_t)b * DM + ti * 128) * NSEQ + (size_t)s * KC;
    const __half* __restrict__ Bbase =
        g_Xt + ((size_t)b * DM + tj * 128) * NSEQ + (size_t)s * KC;

    const int a_row = wm * 64 + ((lane >> 3) & 1) * 8 + (lane & 7);
    const int a_byt = ((lane >> 4) & 1) * 16;
    const int b_row = wn * 32 + ((lane >> 4) & 1) * 8 + (lane & 7);
    const int b_byt = ((lane >> 3) & 1) * 16;

    float acc[4][4][4];
#pragma unroll
    for (int mt = 0; mt < 4; mt++)
#pragma unroll
        for (int nt = 0; nt < 4; nt++)
#pragma unroll
            for (int q = 0; q < 4; q++) acc[mt][nt][q] = 0.f;

    NT_STAGE(Abase, Bbase, NSEQ, 0, 0);

    const int NCH = KC / 64;     // 8
    for (int kc = 0; kc < NCH; kc++) {
        const int cur = kc & 1;
        if (kc + 1 < NCH) {
            NT_STAGE(Abase, Bbase, NSEQ, kc + 1, cur ^ 1);
            CP_WAIT(1);
        } else {
            CP_WAIT(0);
        }
        __syncthreads();

        const uint32_t abase = sb + SM_A + cur * 16384;
        const uint32_t bbase = sb + SM_B + cur * 16384;
#pragma unroll
        for (int kk = 0; kk < 4; kk++) {
            uint32_t a[4][4], bb[4][2];
#pragma unroll
            for (int mt = 0; mt < 4; mt++) {
                uint32_t off = (uint32_t)((a_row + mt * 16) * 128 + kk * 32 + a_byt);
                ldmx4(a[mt], abase + SW128(off));
            }
#pragma unroll
            for (int p = 0; p < 2; p++) {
                uint32_t off = (uint32_t)((b_row + p * 16) * 128 + kk * 32 + b_byt);
                uint32_t r[4];
                ldmx4(r, bbase + SW128(off));
                bb[p * 2][0] = r[0]; bb[p * 2][1] = r[1];
                bb[p * 2 + 1][0] = r[2]; bb[p * 2 + 1][1] = r[3];
            }
#pragma unroll
            for (int mt = 0; mt < 4; mt++)
#pragma unroll
                for (int nt = 0; nt < 4; nt++)
                    mma16816(acc[mt][nt], a[mt], bb[nt]);
        }
        __syncthreads();
    }

    float* C = g_P + ((size_t)(s * BB + b)) * DM * DM;
    const int g = lane >> 2;
    const int t = lane & 3;
#pragma unroll
    for (int mt = 0; mt < 4; mt++) {
        const int r = ti * 128 + wm * 64 + mt * 16 + g;
#pragma unroll
        for (int nt = 0; nt < 4; nt++) {
            const int c = tj * 128 + wn * 32 + nt * 8 + t * 2;
            *(float2*)(C + (size_t)r * DM + c) =
                make_float2(acc[mt][nt][0], acc[mt][nt][1]);
            *(float2*)(C + (size_t)(r + 8) * DM + c) =
                make_float2(acc[mt][nt][2], acc[mt][nt][3]);
        }
    }
}

// split-K reduce + symmetric mirror, fp16 output
__global__ void reduce_g_kernel()
{
    const int idx = blockIdx.x * 256 + threadIdx.x;
    const int b = idx >> 18;
    const int r = idx & (DM * DM - 1);
    const int i = r >> 9;
    const int j = r & 511;
    if (j < i) return;
    float s = 0.f;
#pragma unroll
    for (int sp = 0; sp < SPLITK; sp++)
        s += g_P[((size_t)(sp * BB + b)) * DM * DM + r];
    __half h = __float2half_rn(s);
    g_Gh[(size_t)b * DM * DM + (size_t)i * DM + j] = h;
    g_Gh[(size_t)b * DM * DM + (size_t)j * DM + i] = h;
}

// ============================================================================
// mean over n of X: float4 per thread, 32 chunks of 256 rows
// ============================================================================
__global__ void meanx1_kernel(const float* __restrict__ X)
{
    const int b  = blockIdx.x;
    const int ch = blockIdx.z;
    const int j  = threadIdx.x * 4;
    const float* base = X + ((size_t)b * NSEQ + (size_t)ch * 256) * DM + j;
    float4 s0 = make_float4(0.f, 0.f, 0.f, 0.f);
    float4 s1 = s0, s2 = s0, s3 = s0;
    for (int i = 0; i < 256; i += 4) {
        float4 v0 = *(const float4*)(base + (size_t)(i + 0) * DM);
        float4 v1 = *(const float4*)(base + (size_t)(i + 1) * DM);
        float4 v2 = *(const float4*)(base + (size_t)(i + 2) * DM);
        float4 v3 = *(const float4*)(base + (size_t)(i + 3) * DM);
        s0.x += v0.x; s0.y += v0.y; s0.z += v0.z; s0.w += v0.w;
        s1.x += v1.x; s1.y += v1.y; s1.z += v1.z; s1.w += v1.w;
        s2.x += v2.x; s2.y += v2.y; s2.z += v2.z; s2.w += v2.w;
        s3.x += v3.x; s3.y += v3.y; s3.z += v3.z; s3.w += v3.w;
    }
    float4 r = make_float4((s0.x + s1.x) + (s2.x + s3.x),
                           (s0.y + s1.y) + (s2.y + s3.y),
                           (s0.z + s1.z) + (s2.z + s3.z),
                           (s0.w + s1.w) + (s2.w + s3.w));
    *(float4*)(g_Pm + (b * MCH + ch) * DM + j) = r;
}

// fused: xm = mean(X) (from partials) then first = xm @ Wv^T.  grid (BB), 512 thr
__global__ void meanfirst_kernel(const float* __restrict__ Wv)
{
    __shared__ float xm[DM];
    const int b = blockIdx.x;
    const int t = threadIdx.x;
    float s = 0.f;
#pragma unroll
    for (int c = 0; c < MCH; c++) s += g_Pm[(b * MCH + c) * DM + t];
    xm[t] = s * (1.0f / (float)NSEQ);
    __syncthreads();

    const int wid  = t >> 5;
    const int lane = t & 31;
#pragma unroll
    for (int jj = 0; jj < 32; jj++) {
        const int j = wid * 32 + jj;
        const float* w = Wv + (size_t)j * DM;
        float a = 0.f;
        for (int k = lane; k < DM; k += 32) a += xm[k] * w[k];
#pragma unroll
        for (int o = 16; o; o >>= 1) a += __shfl_xor_sync(0xFFFFFFFFu, a, o);
        if (lane == 0) g_first[b * DM + j] = a;
    }
}

// ============================================================================
// small batched 512^3 GEMM on fp16 HMMA (NT template; G symmetric makes
// mode 0 NT-form). mode 0: M1[b] = Wvh @ Gh[b]; mode 1: KVt[b] = M1h[b] @ Wth^T.
// grid (4, 4, BB), 256 threads, K = 512 (8 chunks).
// ============================================================================
__global__ void __launch_bounds__(256, 2) small_mma_kernel(int mode)
{
    extern __shared__ char smem[];
    const uint32_t sb = smem_to_u32(smem);
    const int tid  = threadIdx.x;
    const int wid  = tid >> 5;
    const int lane = tid & 31;
    const int wm   = wid >> 2;
    const int wn   = wid & 3;
    const int i0   = blockIdx.x * 128;
    const int j0   = blockIdx.y * 128;
    const int b    = blockIdx.z;
    const size_t bo = (size_t)b * DM * DM;
    const __half* __restrict__ Abase =
        ((mode == 0) ? g_Wvh : (g_M1h + bo)) + (size_t)i0 * DM;
    const __half* __restrict__ Bbase =
        ((mode == 0) ? (g_Gh + bo) : g_Wth) + (size_t)j0 * DM;
    __half* __restrict__ C = ((mode == 0) ? g_M1h : g_KVh) + bo;

    const int a_row = wm * 64 + ((lane >> 3) & 1) * 8 + (lane & 7);
    const int a_byt = ((lane >> 4) & 1) * 16;
    const int b_row = wn * 32 + ((lane >> 4) & 1) * 8 + (lane & 7);
    const int b_byt = ((lane >> 3) & 1) * 16;

    float acc[4][4][4];
#pragma unroll
    for (int mt = 0; mt < 4; mt++)
#pragma unroll
        for (int nt = 0; nt < 4; nt++)
#pragma unroll
            for (int q = 0; q < 4; q++) acc[mt][nt][q] = 0.f;

    NT_STAGE(Abase, Bbase, DM, 0, 0);

    const int NCH = DM / 64;     // 8
    for (int kc = 0; kc < NCH; kc++) {
        const int cur = kc & 1;
        if (kc + 1 < NCH) {
            NT_STAGE(Abase, Bbase, DM, kc + 1, cur ^ 1);
            CP_WAIT(1);
        } else {
            CP_WAIT(0);
        }
        __syncthreads();

        const uint32_t abase = sb + SM_A + cur * 16384;
        const uint32_t bbase = sb + SM_B + cur * 16384;
#pragma unroll
        for (int kk = 0; kk < 4; kk++) {
            uint32_t a[4][4], bb[4][2];
#pragma unroll
            for (int mt = 0; mt < 4; mt++) {
                uint32_t off = (uint32_t)((a_row + mt * 16) * 128 + kk * 32 + a_byt);
                ldmx4(a[mt], abase + SW128(off));
            }
#pragma unroll
            for (int p = 0; p < 2; p++) {
                uint32_t off = (uint32_t)((b_row + p * 16) * 128 + kk * 32 + b_byt);
                uint32_t r[4];
                ldmx4(r, bbase + SW128(off));
                bb[p * 2][0] = r[0]; bb[p * 2][1] = r[1];
                bb[p * 2 + 1][0] = r[2]; bb[p * 2 + 1][1] = r[3];
            }
#pragma unroll
            for (int mt = 0; mt < 4; mt++)
#pragma unroll
                for (int nt = 0; nt < 4; nt++)
                    mma16816(acc[mt][nt], a[mt], bb[nt]);
        }
        __syncthreads();
    }

    const int g = lane >> 2;
    const int t = lane & 3;
#pragma unroll
    for (int mt = 0; mt < 4; mt++) {
        const int r = i0 + wm * 64 + mt * 16 + g;
#pragma unroll
        for (int nt = 0; nt < 4; nt++) {
            const int c = j0 + wn * 32 + nt * 8 + t * 2;
            __half2 h0 = __floats2half2_rn(acc[mt][nt][0], acc[mt][nt][1]);
            __half2 h1 = __floats2half2_rn(acc[mt][nt][2], acc[mt][nt][3]);
            *(__half2*)(C + (size_t)r * DM + c) = h0;
            *(__half2*)(C + (size_t)(r + 8) * DM + c) = h1;
        }
    }
}

// ============================================================================
// final GEMM, single-pass fp16 HMMA (validated rounds 9-10):
//   out[m,j] = first[b][j] + scale * sum_k Xh[m,k] KVh[k,j]
// ============================================================================
__global__ void __launch_bounds__(256, 2) final_mma_kernel(float* __restrict__ out)
{
    extern __shared__ char smem[];
    const uint32_t sb = smem_to_u32(smem);
    const int tid  = threadIdx.x;
    const int wid  = tid >> 5;
    const int lane = tid & 31;
    const int wm   = wid >> 2;
    const int wn   = wid & 3;
    const int n0   = blockIdx.x * 128;
    const int m0   = blockIdx.y * 128;
    const int b    = m0 / NSEQ;
    const __half* __restrict__ Abase = g_Xh + (size_t)m0 * DM;
    const __half* __restrict__ Bbase = g_KVh + (size_t)b * DM * DM + (size_t)n0 * DM;

    const int a_row = wm * 64 + ((lane >> 3) & 1) * 8 + (lane & 7);
    const int a_byt = ((lane >> 4) & 1) * 16;
    const int b_row = wn * 32 + ((lane >> 4) & 1) * 8 + (lane & 7);
    const int b_byt = ((lane >> 3) & 1) * 16;

    float acc[4][4][4];
#pragma unroll
    for (int mt = 0; mt < 4; mt++)
#pragma unroll
        for (int nt = 0; nt < 4; nt++)
#pragma unroll
            for (int q = 0; q < 4; q++) acc[mt][nt][q] = 0.f;

    NT_STAGE(Abase, Bbase, DM, 0, 0);

    for (int kc = 0; kc < 8; kc++) {
        const int cur = kc & 1;
        if (kc + 1 < 8) {
            NT_STAGE(Abase, Bbase, DM, kc + 1, cur ^ 1);
            CP_WAIT(1);
        } else {
            CP_WAIT(0);
        }
        __syncthreads();

        const uint32_t abase = sb + SM_A + cur * 16384;
        const uint32_t bbase = sb + SM_B + cur * 16384;
#pragma unroll
        for (int kk = 0; kk < 4; kk++) {
            uint32_t a[4][4], bb[4][2];
#pragma unroll
            for (int mt = 0; mt < 4; mt++) {
                uint32_t off = (uint32_t)((a_row + mt * 16) * 128 + kk * 32 + a_byt);
                ldmx4(a[mt], abase + SW128(off));
            }
#pragma unroll
            for (int p = 0; p < 2; p++) {
                uint32_t off = (uint32_t)((b_row + p * 16) * 128 + kk * 32 + b_byt);
                uint32_t r[4];
                ldmx4(r, bbase + SW128(off));
                bb[p * 2][0] = r[0]; bb[p * 2][1] = r[1];
                bb[p * 2 + 1][0] = r[2]; bb[p * 2 + 1][1] = r[3];
            }
#pragma unroll
            for (int mt = 0; mt < 4; mt++)
#pragma unroll
                for (int nt = 0; nt < 4; nt++)
                    mma16816(acc[mt][nt], a[mt], bb[nt]);
        }
        __syncthreads();
    }

    const float scale = 1.0f / (8192.0f * sqrtf(512.0f));
    const int g = lane >> 2;
    const int t = lane & 3;
#pragma unroll
    for (int mt = 0; mt < 4; mt++) {
        const int r = m0 + wm * 64 + mt * 16 + g;
#pragma unroll
        for (int nt = 0; nt < 4; nt++) {
            const int c = n0 + wn * 32 + nt * 8 + t * 2;
            const float f0 = g_first[b * DM + c];
            const float f1 = g_first[b * DM + c + 1];
            *(float2*)(out + (size_t)r * DM + c) =
                make_float2(f0 + scale * acc[mt][nt][0],
                            f1 + scale * acc[mt][nt][1]);
            *(float2*)(out + (size_t)(r + 8) * DM + c) =
                make_float2(f0 + scale * acc[mt][nt][2],
                            f1 + scale * acc[mt][nt][3]);
        }
    }
}

// ============================================================================
extern "C" void kernel_launch(void* const* d_in, const int* in_sizes, int n_in,
                              void* d_out, int out_size)
{
    (void)in_sizes; (void)n_in; (void)out_size;
    const float* X  = (const float*)d_in[0];
    const float* Wv = (const float*)d_in[1];
    const float* Wt = (const float*)d_in[2];
    float* out = (float*)d_out;

    cudaFuncSetAttribute(final_mma_kernel,
                         cudaFuncAttributeMaxDynamicSharedMemorySize, MMA_SMEM);
    cudaFuncSetAttribute(xtx_mma_kernel,
                         cudaFuncAttributeMaxDynamicSharedMemorySize, MMA_SMEM);
    cudaFuncSetAttribute(small_mma_kernel,
                         cudaFuncAttributeMaxDynamicSharedMemorySize, MMA_SMEM);

    // 0) fp16 conversions (X + transpose; weights)
    convert_x_kernel<<<dim3(NSEQ / 64, DM / 64, BB), 256>>>(X);
    convert_w_kernel<<<dim3(256), 256>>>(Wv, Wt);
    // 1) G[b] = X[b]^T X[b]  (fp16 HMMA, split-K=16, upper-triangle)
    xtx_mma_kernel<<<dim3(10, BB * SPLITK), 256, MMA_SMEM>>>();
    // 2) mean over n of X, then first = mean(X) @ Wv^T (fused)
    meanx1_kernel<<<dim3(BB, 1, MCH), 128>>>(X);
    meanfirst_kernel<<<dim3(BB), 512>>>(Wv);
    // 3) reduce + mirror G -> fp16
    reduce_g_kernel<<<dim3((BB * DM * DM) / 256), 256>>>();
    // 4) M1[b] = Wv @ G[b]; KVt[b] = M1[b] @ Wtheta^T  (fp16 HMMA)
    small_mma_kernel<<<dim3(4, 4, BB), 256, MMA_SMEM>>>(0);
    small_mma_kernel<<<dim3(4, 4, BB), 256, MMA_SMEM>>>(1);
    // 5) out = first + scale * X @ KV   (fp16 HMMA)
    final_mma_kernel<<<dim3(DM / 128, MTOT / 128), 256, MMA_SMEM>>>(out);
}

// round 12
// speedup vs baseline: 4.0726x; 1.2349x over previous
#include <cuda_runtime.h>
#include <cuda_fp16.h>
#include <math.h>
#include <stdint.h>

#define BB     4
#define NSEQ   8192
#define DM     512
#define MTOT   (BB * NSEQ)       // 32768
#define SPLITK 16
#define KC     (NSEQ / SPLITK)   // 512
#define NCHK   (NSEQ / 64)       // 128 mean partial chunks (one per n-block)

// ---------------- scratch (static device memory; referenced ONLY from device
// code — host-side use of these symbols silently hits host memory via ATS) ---
__device__ float g_P [SPLITK * BB * DM * DM];   // X^T X split-K partials
__device__ float g_Pm[BB * NCHK * DM];          // column-sum partials (fused)
__device__ float g_first[BB * DM];
__device__ __half g_Xh [(size_t)MTOT * DM];     // fp16 X       [b*n][d]
__device__ __half g_Xt [(size_t)BB * DM * NSEQ];// fp16 X^T     [b][d][n]
__device__ __half g_Gh [BB * DM * DM];          // fp16 G = X^T X (symmetric)
__device__ __half g_M1h[BB * DM * DM];          // fp16 Wv @ G
__device__ __half g_KVh[BB * DM * DM];          // fp16 KV^T    [j][k]
__device__ __half g_Wvh[DM * DM];               // fp16 Wv
__device__ __half g_Wth[DM * DM];               // fp16 Wtheta

__constant__ int c_ti[10] = {0,0,0,0,1,1,1,2,2,3};
__constant__ int c_tj[10] = {0,1,2,3,1,2,3,2,3,3};

#define SW128(x) ((x) ^ (((x) >> 3) & 0x70))

__device__ __forceinline__ uint32_t smem_to_u32(const void* p) {
    uint32_t a;
    asm("{ .reg .u64 t; cvta.to.shared.u64 t, %1; cvt.u32.u64 %0, t; }"
        : "=r"(a) : "l"(p));
    return a;
}
__device__ __forceinline__ void ldmx4(uint32_t r[4], uint32_t addr) {
    asm volatile("ldmatrix.sync.aligned.m8n8.x4.shared.b16 {%0,%1,%2,%3}, [%4];"
        : "=r"(r[0]), "=r"(r[1]), "=r"(r[2]), "=r"(r[3]) : "r"(addr));
}
__device__ __forceinline__ void mma16816(float c[4], const uint32_t a[4],
                                         const uint32_t b[2]) {
    asm volatile("mma.sync.aligned.m16n8k16.row.col.f32.f16.f16.f32 "
        "{%0,%1,%2,%3}, {%4,%5,%6,%7}, {%8,%9}, {%0,%1,%2,%3};"
        : "+f"(c[0]), "+f"(c[1]), "+f"(c[2]), "+f"(c[3])
        : "r"(a[0]), "r"(a[1]), "r"(a[2]), "r"(a[3]), "r"(b[0]), "r"(b[1]));
}
__device__ __forceinline__ void cp_async16(uint32_t dst, const void* src) {
    asm volatile("cp.async.cg.shared.global [%0], [%1], 16;"
        :: "r"(dst), "l"(src) : "memory");
}
#define CP_COMMIT() asm volatile("cp.async.commit_group;" ::: "memory")
#define CP_WAIT(n)  asm volatile("cp.async.wait_group %0;" :: "n"(n) : "memory")

#define SM_A 0                    // 2 bufs x 16384
#define SM_B 32768                // 2 bufs x 16384
#define MMA_SMEM 65536

// generic NT stage
#define NT_STAGE(Abase, Bbase, stride, kc, buf) do { \
        _Pragma("unroll") \
        for (int i = tid; i < 2048; i += 256) { \
            const int arr = i >> 10; \
            const int idx = i & 1023; \
            const int row = idx >> 3; \
            const int cg  = idx & 7; \
            const uint32_t sw = SW128((uint32_t)(row * 128 + cg * 16)); \
            const uint32_t dst = sb + (arr ? SM_B : SM_A) + (buf) * 16384 + sw; \
            const __half* src = (arr ? (Bbase) : (Abase)) \
                + (size_t)row * (stride) + (kc) * 64 + cg * 8; \
            cp_async16(dst, src); \
        } \
        CP_COMMIT(); \
    } while (0)

// ============================================================================
// fp16 conversion of X + fused transpose + fused column-sum partials.
// grid (NSEQ/64, DM/64, BB), 256 threads, 64x64 tiles via smem.
// Each thread owns a fixed 4-column group (cq) and 4 rows -> float4 partial;
// smem reduction collapses the 64 rows; threads 0..63 emit per-column sums.
// ============================================================================
__global__ void convert_x_kernel(const float* __restrict__ X)
{
    __shared__ __half s[64][72];
    __shared__ float  psum[16][64];     // [row-group][d-local]
    const int b  = blockIdx.z;
    const int n0 = blockIdx.x * 64;
    const int d0 = blockIdx.y * 64;
    const int t  = threadIdx.x;

    float4 cs = make_float4(0.f, 0.f, 0.f, 0.f);
#pragma unroll
    for (int i = t; i < 1024; i += 256) {
        const int row = i >> 4;          // n-local (t>>4 + 16k)
        const int cq  = (i & 15) << 2;   // d-local (fixed per thread)
        float4 v = *(const float4*)(X + ((size_t)b * NSEQ + n0 + row) * DM + d0 + cq);
        cs.x += v.x; cs.y += v.y; cs.z += v.z; cs.w += v.w;
        __half h0 = __float2half_rn(v.x), h1 = __float2half_rn(v.y);
        __half h2 = __float2half_rn(v.z), h3 = __float2half_rn(v.w);
        uint2 u; __half* ph = (__half*)&u;
        ph[0] = h0; ph[1] = h1; ph[2] = h2; ph[3] = h3;
        *(uint2*)(g_Xh + ((size_t)b * NSEQ + n0 + row) * DM + d0 + cq) = u;
        s[cq + 0][row] = h0; s[cq + 1][row] = h1;
        s[cq + 2][row] = h2; s[cq + 3][row] = h3;
    }
    *(float4*)&psum[t >> 4][(t & 15) << 2] = cs;
    __syncthreads();

    // transpose-write X^T
#pragma unroll
    for (int i = t; i < 1024; i += 256) {
        const int dr = i >> 4;
        const int nq = (i & 15) << 2;
        uint2 u; __half* ph = (__half*)&u;
        ph[0] = s[dr][nq]; ph[1] = s[dr][nq + 1];
        ph[2] = s[dr][nq + 2]; ph[3] = s[dr][nq + 3];
        *(uint2*)(g_Xt + ((size_t)b * DM + d0 + dr) * NSEQ + n0 + nq) = u;
    }

    // finish column sums: 64 threads, one column each
    if (t < 64) {
        float v = 0.f;
#pragma unroll
        for (int rg = 0; rg < 16; rg++) v += psum[rg][t];
        g_Pm[((size_t)b * NCHK + blockIdx.x) * DM + d0 + t] = v;
    }
}

// fp16 conversion of Wv / Wtheta. grid 256, 256 thr, 8 elems/thread.
__global__ void convert_w_kernel(const float* __restrict__ Wv,
                                 const float* __restrict__ Wt)
{
    const int blk = blockIdx.x;
    const float* src = (blk < 128) ? Wv : Wt;
    __half* dst = (blk < 128) ? g_Wvh : g_Wth;
    const size_t base = ((size_t)(blk & 127) * 256 + threadIdx.x) * 8;
    float4 v0 = *(const float4*)(src + base);
    float4 v1 = *(const float4*)(src + base + 4);
    uint4 u; __half* ph = (__half*)&u;
    ph[0] = __float2half_rn(v0.x); ph[1] = __float2half_rn(v0.y);
    ph[2] = __float2half_rn(v0.z); ph[3] = __float2half_rn(v0.w);
    ph[4] = __float2half_rn(v1.x); ph[5] = __float2half_rn(v1.y);
    ph[6] = __float2half_rn(v1.z); ph[7] = __float2half_rn(v1.w);
    *(uint4*)(dst + base) = u;
}

// ============================================================================
// X^T X on fp16 HMMA: P[s][b][i][j] = sum_{k in chunk s} Xt[b,i,k] Xt[b,j,k]
// grid (10, BB*SPLITK), 256 threads, K = 512 per CTA (8 chunks of 64).
// ============================================================================
__global__ void __launch_bounds__(256, 2) xtx_mma_kernel()
{
    extern __shared__ char smem[];
    const uint32_t sb = smem_to_u32(smem);
    const int tid  = threadIdx.x;
    const int wid  = tid >> 5;
    const int lane = tid & 31;
    const int wm   = wid >> 2;
    const int wn   = wid & 3;
    const int ti   = c_ti[blockIdx.x];
    const int tj   = c_tj[blockIdx.x];
    const int b    = blockIdx.y / SPLITK;
    const int s    = blockIdx.y % SPLITK;
    const __half* __restrict__ Abase =
        g_Xt + ((size_t)b * DM + ti * 128) * NSEQ + (size_t)s * KC;
    const __half* __restrict__ Bbase =
        g_Xt + ((size_t)b * DM + tj * 128) * NSEQ + (size_t)s * KC;

    const int a_row = wm * 64 + ((lane >> 3) & 1) * 8 + (lane & 7);
    const int a_byt = ((lane >> 4) & 1) * 16;
    const int b_row = wn * 32 + ((lane >> 4) & 1) * 8 + (lane & 7);
    const int b_byt = ((lane >> 3) & 1) * 16;

    float acc[4][4][4];
#pragma unroll
    for (int mt = 0; mt < 4; mt++)
#pragma unroll
        for (int nt = 0; nt < 4; nt++)
#pragma unroll
            for (int q = 0; q < 4; q++) acc[mt][nt][q] = 0.f;

    NT_STAGE(Abase, Bbase, NSEQ, 0, 0);

    const int NCH = KC / 64;     // 8
    for (int kc = 0; kc < NCH; kc++) {
        const int cur = kc & 1;
        if (kc + 1 < NCH) {
            NT_STAGE(Abase, Bbase, NSEQ, kc + 1, cur ^ 1);
            CP_WAIT(1);
        } else {
            CP_WAIT(0);
        }
        __syncthreads();

        const uint32_t abase = sb + SM_A + cur * 16384;
        const uint32_t bbase = sb + SM_B + cur * 16384;
#pragma unroll
        for (int kk = 0; kk < 4; kk++) {
            uint32_t a[4][4], bb[4][2];
#pragma unroll
            for (int mt = 0; mt < 4; mt++) {
                uint32_t off = (uint32_t)((a_row + mt * 16) * 128 + kk * 32 + a_byt);
                ldmx4(a[mt], abase + SW128(off));
            }
#pragma unroll
            for (int p = 0; p < 2; p++) {
                uint32_t off = (uint32_t)((b_row + p * 16) * 128 + kk * 32 + b_byt);
                uint32_t r[4];
                ldmx4(r, bbase + SW128(off));
                bb[p * 2][0] = r[0]; bb[p * 2][1] = r[1];
                bb[p * 2 + 1][0] = r[2]; bb[p * 2 + 1][1] = r[3];
            }
#pragma unroll
            for (int mt = 0; mt < 4; mt++)
#pragma unroll
                for (int nt = 0; nt < 4; nt++)
                    mma16816(acc[mt][nt], a[mt], bb[nt]);
        }
        __syncthreads();
    }

    float* C = g_P + ((size_t)(s * BB + b)) * DM * DM;
    const int g = lane >> 2;
    const int t = lane & 3;
#pragma unroll
    for (int mt = 0; mt < 4; mt++) {
        const int r = ti * 128 + wm * 64 + mt * 16 + g;
#pragma unroll
        for (int nt = 0; nt < 4; nt++) {
            const int c = tj * 128 + wn * 32 + nt * 8 + t * 2;
            *(float2*)(C + (size_t)r * DM + c) =
                make_float2(acc[mt][nt][0], acc[mt][nt][1]);
            *(float2*)(C + (size_t)(r + 8) * DM + c) =
                make_float2(acc[mt][nt][2], acc[mt][nt][3]);
        }
    }
}

// split-K reduce + symmetric mirror, fp16 output
__global__ void reduce_g_kernel()
{
    const int idx = blockIdx.x * 256 + threadIdx.x;
    const int b = idx >> 18;
    const int r = idx & (DM * DM - 1);
    const int i = r >> 9;
    const int j = r & 511;
    if (j < i) return;
    float s = 0.f;
#pragma unroll
    for (int sp = 0; sp < SPLITK; sp++)
        s += g_P[((size_t)(sp * BB + b)) * DM * DM + r];
    __half h = __float2half_rn(s);
    g_Gh[(size_t)b * DM * DM + (size_t)i * DM + j] = h;
    g_Gh[(size_t)b * DM * DM + (size_t)j * DM + i] = h;
}

// fused: xm = mean(X) (from 128 partial chunks), first = xm @ Wv^T.
// grid (BB), 512 threads
__global__ void meanfirst_kernel(const float* __restrict__ Wv)
{
    __shared__ float xm[DM];
    const int b = blockIdx.x;
    const int t = threadIdx.x;
    float s = 0.f;
    for (int c = 0; c < NCHK; c++) s += g_Pm[((size_t)b * NCHK + c) * DM + t];
    xm[t] = s * (1.0f / (float)NSEQ);
    __syncthreads();

    const int wid  = t >> 5;
    const int lane = t & 31;
#pragma unroll
    for (int jj = 0; jj < 32; jj++) {
        const int j = wid * 32 + jj;
        const float* w = Wv + (size_t)j * DM;
        float a = 0.f;
        for (int k = lane; k < DM; k += 32) a += xm[k] * w[k];
#pragma unroll
        for (int o = 16; o; o >>= 1) a += __shfl_xor_sync(0xFFFFFFFFu, a, o);
        if (lane == 0) g_first[b * DM + j] = a;
    }
}

// ============================================================================
// small batched 512^3 GEMM on fp16 HMMA (NT template; G symmetric).
// mode 0: M1[b] = Wvh @ Gh[b]; mode 1: KVt[b] = M1h[b] @ Wth^T.
// grid (4, 4, BB), 256 threads, K = 512 (8 chunks).
// ============================================================================
__global__ void __launch_bounds__(256, 2) small_mma_kernel(int mode)
{
    extern __shared__ char smem[];
    const uint32_t sb = smem_to_u32(smem);
    const int tid  = threadIdx.x;
    const int wid  = tid >> 5;
    const int lane = tid & 31;
    const int wm   = wid >> 2;
    const int wn   = wid & 3;
    const int i0   = blockIdx.x * 128;
    const int j0   = blockIdx.y * 128;
    const int b    = blockIdx.z;
    const size_t bo = (size_t)b * DM * DM;
    const __half* __restrict__ Abase =
        ((mode == 0) ? g_Wvh : (g_M1h + bo)) + (size_t)i0 * DM;
    const __half* __restrict__ Bbase =
        ((mode == 0) ? (g_Gh + bo) : g_Wth) + (size_t)j0 * DM;
    __half* __restrict__ C = ((mode == 0) ? g_M1h : g_KVh) + bo;

    const int a_row = wm * 64 + ((lane >> 3) & 1) * 8 + (lane & 7);
    const int a_byt = ((lane >> 4) & 1) * 16;
    const int b_row = wn * 32 + ((lane >> 4) & 1) * 8 + (lane & 7);
    const int b_byt = ((lane >> 3) & 1) * 16;

    float acc[4][4][4];
#pragma unroll
    for (int mt = 0; mt < 4; mt++)
#pragma unroll
        for (int nt = 0; nt < 4; nt++)
#pragma unroll
            for (int q = 0; q < 4; q++) acc[mt][nt][q] = 0.f;

    NT_STAGE(Abase, Bbase, DM, 0, 0);

    const int NCH = DM / 64;     // 8
    for (int kc = 0; kc < NCH; kc++) {
        const int cur = kc & 1;
        if (kc + 1 < NCH) {
            NT_STAGE(Abase, Bbase, DM, kc + 1, cur ^ 1);
            CP_WAIT(1);
        } else {
            CP_WAIT(0);
        }
        __syncthreads();

        const uint32_t abase = sb + SM_A + cur * 16384;
        const uint32_t bbase = sb + SM_B + cur * 16384;
#pragma unroll
        for (int kk = 0; kk < 4; kk++) {
            uint32_t a[4][4], bb[4][2];
#pragma unroll
            for (int mt = 0; mt < 4; mt++) {
                uint32_t off = (uint32_t)((a_row + mt * 16) * 128 + kk * 32 + a_byt);
                ldmx4(a[mt], abase + SW128(off));
            }
#pragma unroll
            for (int p = 0; p < 2; p++) {
                uint32_t off = (uint32_t)((b_row + p * 16) * 128 + kk * 32 + b_byt);
                uint32_t r[4];
                ldmx4(r, bbase + SW128(off));
                bb[p * 2][0] = r[0]; bb[p * 2][1] = r[1];
                bb[p * 2 + 1][0] = r[2]; bb[p * 2 + 1][1] = r[3];
            }
#pragma unroll
            for (int mt = 0; mt < 4; mt++)
#pragma unroll
                for (int nt = 0; nt < 4; nt++)
                    mma16816(acc[mt][nt], a[mt], bb[nt]);
        }
        __syncthreads();
    }

    const int g = lane >> 2;
    const int t = lane & 3;
#pragma unroll
    for (int mt = 0; mt < 4; mt++) {
        const int r = i0 + wm * 64 + mt * 16 + g;
#pragma unroll
        for (int nt = 0; nt < 4; nt++) {
            const int c = j0 + wn * 32 + nt * 8 + t * 2;
            __half2 h0 = __floats2half2_rn(acc[mt][nt][0], acc[mt][nt][1]);
            __half2 h1 = __floats2half2_rn(acc[mt][nt][2], acc[mt][nt][3]);
            *(__half2*)(C + (size_t)r * DM + c) = h0;
            *(__half2*)(C + (size_t)(r + 8) * DM + c) = h1;
        }
    }
}

// ============================================================================
// final GEMM, single-pass fp16 HMMA:
//   out[m,j] = first[b][j] + scale * sum_k Xh[m,k] KVh[k,j]
// ============================================================================
__global__ void __launch_bounds__(256, 2) final_mma_kernel(float* __restrict__ out)
{
    extern __shared__ char smem[];
    const uint32_t sb = smem_to_u32(smem);
    const int tid  = threadIdx.x;
    const int wid  = tid >> 5;
    const int lane = tid & 31;
    const int wm   = wid >> 2;
    const int wn   = wid & 3;
    const int n0   = blockIdx.x * 128;
    const int m0   = blockIdx.y * 128;
    const int b    = m0 / NSEQ;
    const __half* __restrict__ Abase = g_Xh + (size_t)m0 * DM;
    const __half* __restrict__ Bbase = g_KVh + (size_t)b * DM * DM + (size_t)n0 * DM;

    const int a_row = wm * 64 + ((lane >> 3) & 1) * 8 + (lane & 7);
    const int a_byt = ((lane >> 4) & 1) * 16;
    const int b_row = wn * 32 + ((lane >> 4) & 1) * 8 + (lane & 7);
    const int b_byt = ((lane >> 3) & 1) * 16;

    float acc[4][4][4];
#pragma unroll
    for (int mt = 0; mt < 4; mt++)
#pragma unroll
        for (int nt = 0; nt < 4; nt++)
#pragma unroll
            for (int q = 0; q < 4; q++) acc[mt][nt][q] = 0.f;

    NT_STAGE(Abase, Bbase, DM, 0, 0);

    for (int kc = 0; kc < 8; kc++) {
        const int cur = kc & 1;
        if (kc + 1 < 8) {
            NT_STAGE(Abase, Bbase, DM, kc + 1, cur ^ 1);
            CP_WAIT(1);
        } else {
            CP_WAIT(0);
        }
        __syncthreads();

        const uint32_t abase = sb + SM_A + cur * 16384;
        const uint32_t bbase = sb + SM_B + cur * 16384;
#pragma unroll
        for (int kk = 0; kk < 4; kk++) {
            uint32_t a[4][4], bb[4][2];
#pragma unroll
            for (int mt = 0; mt < 4; mt++) {
                uint32_t off = (uint32_t)((a_row + mt * 16) * 128 + kk * 32 + a_byt);
                ldmx4(a[mt], abase + SW128(off));
            }
#pragma unroll
            for (int p = 0; p < 2; p++) {
                uint32_t off = (uint32_t)((b_row + p * 16) * 128 + kk * 32 + b_byt);
                uint32_t r[4];
                ldmx4(r, bbase + SW128(off));
                bb[p * 2][0] = r[0]; bb[p * 2][1] = r[1];
                bb[p * 2 + 1][0] = r[2]; bb[p * 2 + 1][1] = r[3];
            }
#pragma unroll
            for (int mt = 0; mt < 4; mt++)
#pragma unroll
                for (int nt = 0; nt < 4; nt++)
                    mma16816(acc[mt][nt], a[mt], bb[nt]);
        }
        __syncthreads();
    }

    const float scale = 1.0f / (8192.0f * sqrtf(512.0f));
    const int g = lane >> 2;
    const int t = lane & 3;
#pragma unroll
    for (int mt = 0; mt < 4; mt++) {
        const int r = m0 + wm * 64 + mt * 16 + g;
#pragma unroll
        for (int nt = 0; nt < 4; nt++) {
            const int c = n0 + wn * 32 + nt * 8 + t * 2;
            const float f0 = g_first[b * DM + c];
            const float f1 = g_first[b * DM + c + 1];
            *(float2*)(out + (size_t)r * DM + c) =
                make_float2(f0 + scale * acc[mt][nt][0],
                            f1 + scale * acc[mt][nt][1]);
            *(float2*)(out + (size_t)(r + 8) * DM + c) =
                make_float2(f0 + scale * acc[mt][nt][2],
                            f1 + scale * acc[mt][nt][3]);
        }
    }
}

// ============================================================================
extern "C" void kernel_launch(void* const* d_in, const int* in_sizes, int n_in,
                              void* d_out, int out_size)
{
    (void)in_sizes; (void)n_in; (void)out_size;
    const float* X  = (const float*)d_in[0];
    const float* Wv = (const float*)d_in[1];
    const float* Wt = (const float*)d_in[2];
    float* out = (float*)d_out;

    cudaFuncSetAttribute(final_mma_kernel,
                         cudaFuncAttributeMaxDynamicSharedMemorySize, MMA_SMEM);
    cudaFuncSetAttribute(xtx_mma_kernel,
                         cudaFuncAttributeMaxDynamicSharedMemorySize, MMA_SMEM);
    cudaFuncSetAttribute(small_mma_kernel,
                         cudaFuncAttributeMaxDynamicSharedMemorySize, MMA_SMEM);

    // 0) fp16 conversions (X + transpose + fused column sums; weights)
    convert_x_kernel<<<dim3(NSEQ / 64, DM / 64, BB), 256>>>(X);
    convert_w_kernel<<<dim3(256), 256>>>(Wv, Wt);
    // 1) G[b] = X[b]^T X[b]  (fp16 HMMA, split-K=16, upper-triangle)
    xtx_mma_kernel<<<dim3(10, BB * SPLITK), 256, MMA_SMEM>>>();
    // 2) first = mean(X) @ Wv^T  (partials came from convert_x)
    meanfirst_kernel<<<dim3(BB), 512>>>(Wv);
    // 3) reduce + mirror G -> fp16
    reduce_g_kernel<<<dim3((BB * DM * DM) / 256), 256>>>();
    // 4) M1[b] = Wv @ G[b]; KVt[b] = M1[b] @ Wtheta^T  (fp16 HMMA)
    small_mma_kernel<<<dim3(4, 4, BB), 256, MMA_SMEM>>>(0);
    small_mma_kernel<<<dim3(4, 4, BB), 256, MMA_SMEM>>>(1);
    // 5) out = first + scale * X @ KV   (fp16 HMMA)
    final_mma_kernel<<<dim3(DM / 128, MTOT / 128), 256, MMA_SMEM>>>(out);
}

// round 13
// speedup vs baseline: 5.0595x; 1.2423x over previous
#include <cuda_runtime.h>
#include <cuda_fp16.h>
#include <math.h>
#include <stdint.h>

#define BB     4
#define NSEQ   8192
#define DM     512
#define MTOT   (BB * NSEQ)       // 32768
#define SPLITK 16
#define KC     (NSEQ / SPLITK)   // 512
#define NCHK   (NSEQ / 64)       // 128 mean partial chunks (one per n-block)

// ---------------- scratch (static device memory; referenced ONLY from device
// code — host-side use of these symbols silently hits host memory via ATS) ---
__device__ float g_P [SPLITK * BB * DM * DM];   // X^T X split-K partials
__device__ float g_Pm[BB * NCHK * DM];          // column-sum partials (fused)
__device__ float g_xm[BB * DM];                 // mean over n of X
__device__ float g_first[BB * DM];
__device__ __half g_Xh [(size_t)MTOT * DM];     // fp16 X       [b*n][d]
__device__ __half g_Xt [(size_t)BB * DM * NSEQ];// fp16 X^T     [b][d][n]
__device__ __half g_Gh [BB * DM * DM];          // fp16 G = X^T X (symmetric)
__device__ __half g_M1h[BB * DM * DM];          // fp16 Wv @ G
__device__ __half g_KVh[BB * DM * DM];          // fp16 KV^T    [j][k]
__device__ __half g_Wvh[DM * DM];               // fp16 Wv
__device__ __half g_Wth[DM * DM];               // fp16 Wtheta

__constant__ int c_ti[10] = {0,0,0,0,1,1,1,2,2,3};
__constant__ int c_tj[10] = {0,1,2,3,1,2,3,2,3,3};

#define SW128(x) ((x) ^ (((x) >> 3) & 0x70))

__device__ __forceinline__ uint32_t smem_to_u32(const void* p) {
    uint32_t a;
    asm("{ .reg .u64 t; cvta.to.shared.u64 t, %1; cvt.u32.u64 %0, t; }"
        : "=r"(a) : "l"(p));
    return a;
}
__device__ __forceinline__ void ldmx4(uint32_t r[4], uint32_t addr) {
    asm volatile("ldmatrix.sync.aligned.m8n8.x4.shared.b16 {%0,%1,%2,%3}, [%4];"
        : "=r"(r[0]), "=r"(r[1]), "=r"(r[2]), "=r"(r[3]) : "r"(addr));
}
__device__ __forceinline__ void mma16816(float c[4], const uint32_t a[4],
                                         const uint32_t b[2]) {
    asm volatile("mma.sync.aligned.m16n8k16.row.col.f32.f16.f16.f32 "
        "{%0,%1,%2,%3}, {%4,%5,%6,%7}, {%8,%9}, {%0,%1,%2,%3};"
        : "+f"(c[0]), "+f"(c[1]), "+f"(c[2]), "+f"(c[3])
        : "r"(a[0]), "r"(a[1]), "r"(a[2]), "r"(a[3]), "r"(b[0]), "r"(b[1]));
}
__device__ __forceinline__ void cp_async16(uint32_t dst, const void* src) {
    asm volatile("cp.async.cg.shared.global [%0], [%1], 16;"
        :: "r"(dst), "l"(src) : "memory");
}
#define CP_COMMIT() asm volatile("cp.async.commit_group;" ::: "memory")
#define CP_WAIT(n)  asm volatile("cp.async.wait_group %0;" :: "n"(n) : "memory")

#define SM_A 0                    // 2 bufs x 16384
#define SM_B 32768                // 2 bufs x 16384
#define MMA_SMEM 65536

// generic NT stage
#define NT_STAGE(Abase, Bbase, stride, kc, buf) do { \
        _Pragma("unroll") \
        for (int i = tid; i < 2048; i += 256) { \
            const int arr = i >> 10; \
            const int idx = i & 1023; \
            const int row = idx >> 3; \
            const int cg  = idx & 7; \
            const uint32_t sw = SW128((uint32_t)(row * 128 + cg * 16)); \
            const uint32_t dst = sb + (arr ? SM_B : SM_A) + (buf) * 16384 + sw; \
            const __half* src = (arr ? (Bbase) : (Abase)) \
                + (size_t)row * (stride) + (kc) * 64 + cg * 8; \
            cp_async16(dst, src); \
        } \
        CP_COMMIT(); \
    } while (0)

// ============================================================================
// fp16 conversion of X + fused transpose + fused column-sum partials.
// grid (NSEQ/64, DM/64, BB), 256 threads, 64x64 tiles via smem.
// ============================================================================
__global__ void convert_x_kernel(const float* __restrict__ X)
{
    __shared__ __half s[64][72];
    __shared__ float  psum[16][64];     // [row-group][d-local]
    const int b  = blockIdx.z;
    const int n0 = blockIdx.x * 64;
    const int d0 = blockIdx.y * 64;
    const int t  = threadIdx.x;

    float4 cs = make_float4(0.f, 0.f, 0.f, 0.f);
#pragma unroll
    for (int i = t; i < 1024; i += 256) {
        const int row = i >> 4;          // n-local
        const int cq  = (i & 15) << 2;   // d-local (fixed per thread)
        float4 v = *(const float4*)(X + ((size_t)b * NSEQ + n0 + row) * DM + d0 + cq);
        cs.x += v.x; cs.y += v.y; cs.z += v.z; cs.w += v.w;
        __half h0 = __float2half_rn(v.x), h1 = __float2half_rn(v.y);
        __half h2 = __float2half_rn(v.z), h3 = __float2half_rn(v.w);
        uint2 u; __half* ph = (__half*)&u;
        ph[0] = h0; ph[1] = h1; ph[2] = h2; ph[3] = h3;
        *(uint2*)(g_Xh + ((size_t)b * NSEQ + n0 + row) * DM + d0 + cq) = u;
        s[cq + 0][row] = h0; s[cq + 1][row] = h1;
        s[cq + 2][row] = h2; s[cq + 3][row] = h3;
    }
    *(float4*)&psum[t >> 4][(t & 15) << 2] = cs;
    __syncthreads();

    // transpose-write X^T
#pragma unroll
    for (int i = t; i < 1024; i += 256) {
        const int dr = i >> 4;
        const int nq = (i & 15) << 2;
        uint2 u; __half* ph = (__half*)&u;
        ph[0] = s[dr][nq]; ph[1] = s[dr][nq + 1];
        ph[2] = s[dr][nq + 2]; ph[3] = s[dr][nq + 3];
        *(uint2*)(g_Xt + ((size_t)b * DM + d0 + dr) * NSEQ + n0 + nq) = u;
    }

    // finish column sums: 64 threads, one column each
    if (t < 64) {
        float v = 0.f;
#pragma unroll
        for (int rg = 0; rg < 16; rg++) v += psum[rg][t];
        g_Pm[((size_t)b * NCHK + blockIdx.x) * DM + d0 + t] = v;
    }
}

// fp16 conversion of Wv / Wtheta. grid 256, 256 thr, 8 elems/thread.
__global__ void convert_w_kernel(const float* __restrict__ Wv,
                                 const float* __restrict__ Wt)
{
    const int blk = blockIdx.x;
    const float* src = (blk < 128) ? Wv : Wt;
    __half* dst = (blk < 128) ? g_Wvh : g_Wth;
    const size_t base = ((size_t)(blk & 127) * 256 + threadIdx.x) * 8;
    float4 v0 = *(const float4*)(src + base);
    float4 v1 = *(const float4*)(src + base + 4);
    uint4 u; __half* ph = (__half*)&u;
    ph[0] = __float2half_rn(v0.x); ph[1] = __float2half_rn(v0.y);
    ph[2] = __float2half_rn(v0.z); ph[3] = __float2half_rn(v0.w);
    ph[4] = __float2half_rn(v1.x); ph[5] = __float2half_rn(v1.y);
    ph[6] = __float2half_rn(v1.z); ph[7] = __float2half_rn(v1.w);
    *(uint4*)(dst + base) = u;
}

// ============================================================================
// X^T X on fp16 HMMA: P[s][b][i][j] = sum_{k in chunk s} Xt[b,i,k] Xt[b,j,k]
// grid (10, BB*SPLITK), 256 threads, K = 512 per CTA (8 chunks of 64).
// ============================================================================
__global__ void __launch_bounds__(256, 2) xtx_mma_kernel()
{
    extern __shared__ char smem[];
    const uint32_t sb = smem_to_u32(smem);
    const int tid  = threadIdx.x;
    const int wid  = tid >> 5;
    const int lane = tid & 31;
    const int wm   = wid >> 2;
    const int wn   = wid & 3;
    const int ti   = c_ti[blockIdx.x];
    const int tj   = c_tj[blockIdx.x];
    const int b    = blockIdx.y / SPLITK;
    const int s    = blockIdx.y % SPLITK;
    const __half* __restrict__ Abase =
        g_Xt + ((size_t)b * DM + ti * 128) * NSEQ + (size_t)s * KC;
    const __half* __restrict__ Bbase =
        g_Xt + ((size_t)b * DM + tj * 128) * NSEQ + (size_t)s * KC;

    const int a_row = wm * 64 + ((lane >> 3) & 1) * 8 + (lane & 7);
    const int a_byt = ((lane >> 4) & 1) * 16;
    const int b_row = wn * 32 + ((lane >> 4) & 1) * 8 + (lane & 7);
    const int b_byt = ((lane >> 3) & 1) * 16;

    float acc[4][4][4];
#pragma unroll
    for (int mt = 0; mt < 4; mt++)
#pragma unroll
        for (int nt = 0; nt < 4; nt++)
#pragma unroll
            for (int q = 0; q < 4; q++) acc[mt][nt][q] = 0.f;

    NT_STAGE(Abase, Bbase, NSEQ, 0, 0);

    const int NCH = KC / 64;     // 8
    for (int kc = 0; kc < NCH; kc++) {
        const int cur = kc & 1;
        if (kc + 1 < NCH) {
            NT_STAGE(Abase, Bbase, NSEQ, kc + 1, cur ^ 1);
            CP_WAIT(1);
        } else {
            CP_WAIT(0);
        }
        __syncthreads();

        const uint32_t abase = sb + SM_A + cur * 16384;
        const uint32_t bbase = sb + SM_B + cur * 16384;
#pragma unroll
        for (int kk = 0; kk < 4; kk++) {
            uint32_t a[4][4], bb[4][2];
#pragma unroll
            for (int mt = 0; mt < 4; mt++) {
                uint32_t off = (uint32_t)((a_row + mt * 16) * 128 + kk * 32 + a_byt);
                ldmx4(a[mt], abase + SW128(off));
            }
#pragma unroll
            for (int p = 0; p < 2; p++) {
                uint32_t off = (uint32_t)((b_row + p * 16) * 128 + kk * 32 + b_byt);
                uint32_t r[4];
                ldmx4(r, bbase + SW128(off));
                bb[p * 2][0] = r[0]; bb[p * 2][1] = r[1];
                bb[p * 2 + 1][0] = r[2]; bb[p * 2 + 1][1] = r[3];
            }
#pragma unroll
            for (int mt = 0; mt < 4; mt++)
#pragma unroll
                for (int nt = 0; nt < 4; nt++)
                    mma16816(acc[mt][nt], a[mt], bb[nt]);
        }
        __syncthreads();
    }

    float* C = g_P + ((size_t)(s * BB + b)) * DM * DM;
    const int g = lane >> 2;
    const int t = lane & 3;
#pragma unroll
    for (int mt = 0; mt < 4; mt++) {
        const int r = ti * 128 + wm * 64 + mt * 16 + g;
#pragma unroll
        for (int nt = 0; nt < 4; nt++) {
            const int c = tj * 128 + wn * 32 + nt * 8 + t * 2;
            *(float2*)(C + (size_t)r * DM + c) =
                make_float2(acc[mt][nt][0], acc[mt][nt][1]);
            *(float2*)(C + (size_t)(r + 8) * DM + c) =
                make_float2(acc[mt][nt][2], acc[mt][nt][3]);
        }
    }
}

// split-K reduce + symmetric mirror, fp16 output
__global__ void reduce_g_kernel()
{
    const int idx = blockIdx.x * 256 + threadIdx.x;
    const int b = idx >> 18;
    const int r = idx & (DM * DM - 1);
    const int i = r >> 9;
    const int j = r & 511;
    if (j < i) return;
    float s = 0.f;
#pragma unroll
    for (int sp = 0; sp < SPLITK; sp++)
        s += g_P[((size_t)(sp * BB + b)) * DM * DM + r];
    __half h = __float2half_rn(s);
    g_Gh[(size_t)b * DM * DM + (size_t)i * DM + j] = h;
    g_Gh[(size_t)b * DM * DM + (size_t)j * DM + i] = h;
}

// mean finish: reduce 128 chunks -> g_xm. grid (BB, 4), 128 threads.
__global__ void meanx2_kernel()
{
    const int b = blockIdx.x;
    const int j = blockIdx.y * 128 + threadIdx.x;
    const float* p = g_Pm + (size_t)b * NCHK * DM + j;
    float s0 = 0.f, s1 = 0.f, s2 = 0.f, s3 = 0.f;
#pragma unroll
    for (int c = 0; c < NCHK; c += 4) {
        s0 += p[(size_t)(c + 0) * DM];
        s1 += p[(size_t)(c + 1) * DM];
        s2 += p[(size_t)(c + 2) * DM];
        s3 += p[(size_t)(c + 3) * DM];
    }
    g_xm[b * DM + j] = ((s0 + s1) + (s2 + s3)) * (1.0f / (float)NSEQ);
}

// first[b][j] = xm[b] . Wv[j] for ALL batches at once.
// grid (64), 256 threads (8 warps); warp w owns row j = blk*8+w,
// reads the Wv row once, accumulates 4 batch dots simultaneously.
__global__ void first_kernel(const float* __restrict__ Wv)
{
    __shared__ float xm[BB][DM];
    const int t = threadIdx.x;
    for (int i = t; i < BB * DM; i += 256)
        xm[i >> 9][i & 511] = g_xm[i];
    __syncthreads();

    const int wid  = t >> 5;
    const int lane = t & 31;
    const int j = blockIdx.x * 8 + wid;
    const float* w = Wv + (size_t)j * DM;
    float a0 = 0.f, a1 = 0.f, a2 = 0.f, a3 = 0.f;
    for (int k = lane; k < DM; k += 32) {
        const float wv = w[k];
        a0 += xm[0][k] * wv;
        a1 += xm[1][k] * wv;
        a2 += xm[2][k] * wv;
        a3 += xm[3][k] * wv;
    }
#pragma unroll
    for (int o = 16; o; o >>= 1) {
        a0 += __shfl_xor_sync(0xFFFFFFFFu, a0, o);
        a1 += __shfl_xor_sync(0xFFFFFFFFu, a1, o);
        a2 += __shfl_xor_sync(0xFFFFFFFFu, a2, o);
        a3 += __shfl_xor_sync(0xFFFFFFFFu, a3, o);
    }
    if (lane == 0) {
        g_first[0 * DM + j] = a0;
        g_first[1 * DM + j] = a1;
        g_first[2 * DM + j] = a2;
        g_first[3 * DM + j] = a3;
    }
}

// ============================================================================
// small batched 512^3 GEMM on fp16 HMMA (NT template; G symmetric).
// mode 0: M1[b] = Wvh @ Gh[b]; mode 1: KVt[b] = M1h[b] @ Wth^T.
// grid (4, 4, BB), 256 threads, K = 512 (8 chunks).
// ============================================================================
__global__ void __launch_bounds__(256, 2) small_mma_kernel(int mode)
{
    extern __shared__ char smem[];
    const uint32_t sb = smem_to_u32(smem);
    const int tid  = threadIdx.x;
    const int wid  = tid >> 5;
    const int lane = tid & 31;
    const int wm   = wid >> 2;
    const int wn   = wid & 3;
    const int i0   = blockIdx.x * 128;
    const int j0   = blockIdx.y * 128;
    const int b    = blockIdx.z;
    const size_t bo = (size_t)b * DM * DM;
    const __half* __restrict__ Abase =
        ((mode == 0) ? g_Wvh : (g_M1h + bo)) + (size_t)i0 * DM;
    const __half* __restrict__ Bbase =
        ((mode == 0) ? (g_Gh + bo) : g_Wth) + (size_t)j0 * DM;
    __half* __restrict__ C = ((mode == 0) ? g_M1h : g_KVh) + bo;

    const int a_row = wm * 64 + ((lane >> 3) & 1) * 8 + (lane & 7);
    const int a_byt = ((lane >> 4) & 1) * 16;
    const int b_row = wn * 32 + ((lane >> 4) & 1) * 8 + (lane & 7);
    const int b_byt = ((lane >> 3) & 1) * 16;

    float acc[4][4][4];
#pragma unroll
    for (int mt = 0; mt < 4; mt++)
#pragma unroll
        for (int nt = 0; nt < 4; nt++)
#pragma unroll
            for (int q = 0; q < 4; q++) acc[mt][nt][q] = 0.f;

    NT_STAGE(Abase, Bbase, DM, 0, 0);

    const int NCH = DM / 64;     // 8
    for (int kc = 0; kc < NCH; kc++) {
        const int cur = kc & 1;
        if (kc + 1 < NCH) {
            NT_STAGE(Abase, Bbase, DM, kc + 1, cur ^ 1);
            CP_WAIT(1);
        } else {
            CP_WAIT(0);
        }
        __syncthreads();

        const uint32_t abase = sb + SM_A + cur * 16384;
        const uint32_t bbase = sb + SM_B + cur * 16384;
#pragma unroll
        for (int kk = 0; kk < 4; kk++) {
            uint32_t a[4][4], bb[4][2];
#pragma unroll
            for (int mt = 0; mt < 4; mt++) {
                uint32_t off = (uint32_t)((a_row + mt * 16) * 128 + kk * 32 + a_byt);
                ldmx4(a[mt], abase + SW128(off));
            }
#pragma unroll
            for (int p = 0; p < 2; p++) {
                uint32_t off = (uint32_t)((b_row + p * 16) * 128 + kk * 32 + b_byt);
                uint32_t r[4];
                ldmx4(r, bbase + SW128(off));
                bb[p * 2][0] = r[0]; bb[p * 2][1] = r[1];
                bb[p * 2 + 1][0] = r[2]; bb[p * 2 + 1][1] = r[3];
            }
#pragma unroll
            for (int mt = 0; mt < 4; mt++)
#pragma unroll
                for (int nt = 0; nt < 4; nt++)
                    mma16816(acc[mt][nt], a[mt], bb[nt]);
        }
        __syncthreads();
    }

    const int g = lane >> 2;
    const int t = lane & 3;
#pragma unroll
    for (int mt = 0; mt < 4; mt++) {
        const int r = i0 + wm * 64 + mt * 16 + g;
#pragma unroll
        for (int nt = 0; nt < 4; nt++) {
            const int c = j0 + wn * 32 + nt * 8 + t * 2;
            __half2 h0 = __floats2half2_rn(acc[mt][nt][0], acc[mt][nt][1]);
            __half2 h1 = __floats2half2_rn(acc[mt][nt][2], acc[mt][nt][3]);
            *(__half2*)(C + (size_t)r * DM + c) = h0;
            *(__half2*)(C + (size_t)(r + 8) * DM + c) = h1;
        }
    }
}

// ============================================================================
// final GEMM, single-pass fp16 HMMA:
//   out[m,j] = first[b][j] + scale * sum_k Xh[m,k] KVh[k,j]
// ============================================================================
__global__ void __launch_bounds__(256, 2) final_mma_kernel(float* __restrict__ out)
{
    extern __shared__ char smem[];
    const uint32_t sb = smem_to_u32(smem);
    const int tid  = threadIdx.x;
    const int wid  = tid >> 5;
    const int lane = tid & 31;
    const int wm   = wid >> 2;
    const int wn   = wid & 3;
    const int n0   = blockIdx.x * 128;
    const int m0   = blockIdx.y * 128;
    const int b    = m0 / NSEQ;
    const __half* __restrict__ Abase = g_Xh + (size_t)m0 * DM;
    const __half* __restrict__ Bbase = g_KVh + (size_t)b * DM * DM + (size_t)n0 * DM;

    const int a_row = wm * 64 + ((lane >> 3) & 1) * 8 + (lane & 7);
    const int a_byt = ((lane >> 4) & 1) * 16;
    const int b_row = wn * 32 + ((lane >> 4) & 1) * 8 + (lane & 7);
    const int b_byt = ((lane >> 3) & 1) * 16;

    float acc[4][4][4];
#pragma unroll
    for (int mt = 0; mt < 4; mt++)
#pragma unroll
        for (int nt = 0; nt < 4; nt++)
#pragma unroll
            for (int q = 0; q < 4; q++) acc[mt][nt][q] = 0.f;

    NT_STAGE(Abase, Bbase, DM, 0, 0);

    for (int kc = 0; kc < 8; kc++) {
        const int cur = kc & 1;
        if (kc + 1 < 8) {
            NT_STAGE(Abase, Bbase, DM, kc + 1, cur ^ 1);
            CP_WAIT(1);
        } else {
            CP_WAIT(0);
        }
        __syncthreads();

        const uint32_t abase = sb + SM_A + cur * 16384;
        const uint32_t bbase = sb + SM_B + cur * 16384;
#pragma unroll
        for (int kk = 0; kk < 4; kk++) {
            uint32_t a[4][4], bb[4][2];
#pragma unroll
            for (int mt = 0; mt < 4; mt++) {
                uint32_t off = (uint32_t)((a_row + mt * 16) * 128 + kk * 32 + a_byt);
                ldmx4(a[mt], abase + SW128(off));
            }
#pragma unroll
            for (int p = 0; p < 2; p++) {
                uint32_t off = (uint32_t)((b_row + p * 16) * 128 + kk * 32 + b_byt);
                uint32_t r[4];
                ldmx4(r, bbase + SW128(off));
                bb[p * 2][0] = r[0]; bb[p * 2][1] = r[1];
                bb[p * 2 + 1][0] = r[2]; bb[p * 2 + 1][1] = r[3];
            }
#pragma unroll
            for (int mt = 0; mt < 4; mt++)
#pragma unroll
                for (int nt = 0; nt < 4; nt++)
                    mma16816(acc[mt][nt], a[mt], bb[nt]);
        }
        __syncthreads();
    }

    const float scale = 1.0f / (8192.0f * sqrtf(512.0f));
    const int g = lane >> 2;
    const int t = lane & 3;
#pragma unroll
    for (int mt = 0; mt < 4; mt++) {
        const int r = m0 + wm * 64 + mt * 16 + g;
#pragma unroll
        for (int nt = 0; nt < 4; nt++) {
            const int c = n0 + wn * 32 + nt * 8 + t * 2;
            const float f0 = g_first[b * DM + c];
            const float f1 = g_first[b * DM + c + 1];
            *(float2*)(out + (size_t)r * DM + c) =
                make_float2(f0 + scale * acc[mt][nt][0],
                            f1 + scale * acc[mt][nt][1]);
            *(float2*)(out + (size_t)(r + 8) * DM + c) =
                make_float2(f0 + scale * acc[mt][nt][2],
                            f1 + scale * acc[mt][nt][3]);
        }
    }
}

// ============================================================================
extern "C" void kernel_launch(void* const* d_in, const int* in_sizes, int n_in,
                              void* d_out, int out_size)
{
    (void)in_sizes; (void)n_in; (void)out_size;
    const float* X  = (const float*)d_in[0];
    const float* Wv = (const float*)d_in[1];
    const float* Wt = (const float*)d_in[2];
    float* out = (float*)d_out;

    cudaFuncSetAttribute(final_mma_kernel,
                         cudaFuncAttributeMaxDynamicSharedMemorySize, MMA_SMEM);
    cudaFuncSetAttribute(xtx_mma_kernel,
                         cudaFuncAttributeMaxDynamicSharedMemorySize, MMA_SMEM);
    cudaFuncSetAttribute(small_mma_kernel,
                         cudaFuncAttributeMaxDynamicSharedMemorySize, MMA_SMEM);

    // 0) fp16 conversions (X + transpose + fused column sums; weights)
    convert_x_kernel<<<dim3(NSEQ / 64, DM / 64, BB), 256>>>(X);
    convert_w_kernel<<<dim3(256), 256>>>(Wv, Wt);
    // 1) G[b] = X[b]^T X[b]  (fp16 HMMA, split-K=16, upper-triangle)
    xtx_mma_kernel<<<dim3(10, BB * SPLITK), 256, MMA_SMEM>>>();
    // 2) mean finish + first = mean(X) @ Wv^T (wide grids)
    meanx2_kernel<<<dim3(BB, 4), 128>>>();
    first_kernel<<<dim3(64), 256>>>(Wv);
    // 3) reduce + mirror G -> fp16
    reduce_g_kernel<<<dim3((BB * DM * DM) / 256), 256>>>();
    // 4) M1[b] = Wv @ G[b]; KVt[b] = M1[b] @ Wtheta^T  (fp16 HMMA)
    small_mma_kernel<<<dim3(4, 4, BB), 256, MMA_SMEM>>>(0);
    small_mma_kernel<<<dim3(4, 4, BB), 256, MMA_SMEM>>>(1);
    // 5) out = first + scale * X @ KV   (fp16 HMMA)
    final_mma_kernel<<<dim3(DM / 128, MTOT / 128), 256, MMA_SMEM>>>(out);
}